// round 12
// baseline (speedup 1.0000x reference)
#include <cuda_runtime.h>
#include <cuda_fp16.h>
#include <cstdint>

#define N_NODES 50000
#define N_EDGES 1600000
#define DIM 128
#define NH 8
#define TILE_E 64
#define NTILES (N_EDGES / TILE_E)   // 25000
#define NPER 304                    // persistent CTAs (2 per SM x 152 SMs)
#define PAD 132                     // Eh row stride (floats)
#define PADA 68                     // A tile row stride (half2 units)
#define PADB 136                    // B tile row stride (half2 units)

// ---------------- scratch (static device globals: no alloc allowed) ----------
__device__ float g_Q[(size_t)N_NODES * DIM];
__device__ float g_K[(size_t)N_NODES * DIM];
__device__ float g_V[(size_t)N_NODES * DIM];
__device__ int   g_cnt[N_NODES];
__device__ int   g_base[N_NODES + 1];
__device__ int   g_psrc[N_EDGES];     // slot -> src node
__device__ int   g_pdst[N_EDGES];     // slot -> dst node
__device__ int   g_pinv[N_EDGES];     // slot -> original edge id
__device__ float g_pscore[(size_t)N_EDGES * NH];   // 51 MB
__device__ int   g_idx64;

// ---------------- edge_index dtype detection (int64 vs int32) ----------------
__global__ void detect_idx_kernel(const void* idx) {
    const long long* p = (const long long*)idx;
    int is64 = 1;
    for (int i = 0; i < 64; i++) {
        long long v = p[i];
        if (v < 0 || v >= N_NODES) { is64 = 0; break; }
    }
    g_idx64 = is64;
}

// ---------------- histogram of dst (4 edges per thread) -----------------------
#define CVT_T ((N_EDGES + 3) / 4)   // 400000 threads, each owns edges i0 + u*CVT_T
__global__ __launch_bounds__(256)
void hist_kernel(const void* __restrict__ eidx, int* __restrict__ cnt) {
    const int i0 = blockIdx.x * blockDim.x + threadIdx.x;
    if (i0 >= CVT_T) return;              // R11 bugfix: padded threads duplicated edges
    const bool idx64 = (g_idx64 != 0);
    int d[4];
#pragma unroll
    for (int u = 0; u < 4; u++) {
        const int e = i0 + u * CVT_T;
        if (e < N_EDGES) {
            if (idx64) d[u] = (int)__ldg((const long long*)eidx + (size_t)N_EDGES + e);
            else       d[u] = __ldg((const int*)eidx + N_EDGES + e);
        } else d[u] = -1;
    }
#pragma unroll
    for (int u = 0; u < 4; u++)
        if (d[u] >= 0) atomicAdd(&cnt[d[u]], 1);
}

// ---------------- single-block exclusive scan (1024 threads) ------------------
__global__ __launch_bounds__(1024)
void scan_kernel(const int* __restrict__ cnt, int* __restrict__ base) {
    __shared__ int wsum[32];
    const int tid = threadIdx.x;
    const int lane = tid & 31, wid = tid >> 5;
    const int CH = (N_NODES + 1023) / 1024;   // 49
    const int start = tid * CH;

    int s = 0;
    for (int i = 0; i < CH; i++) {
        const int idx = start + i;
        if (idx < N_NODES) s += cnt[idx];
    }
    int v = s;
#pragma unroll
    for (int d = 1; d < 32; d <<= 1) {
        int n = __shfl_up_sync(0xffffffffu, v, d);
        if (lane >= d) v += n;
    }
    if (lane == 31) wsum[wid] = v;
    __syncthreads();
    if (wid == 0) {
        int wv = wsum[lane];
#pragma unroll
        for (int d = 1; d < 32; d <<= 1) {
            int n = __shfl_up_sync(0xffffffffu, wv, d);
            if (lane >= d) wv += n;
        }
        wsum[lane] = wv;
    }
    __syncthreads();
    int run = v - s + (wid > 0 ? wsum[wid - 1] : 0);
    for (int i = 0; i < CH; i++) {
        const int idx = start + i;
        if (idx < N_NODES) { base[idx] = run; run += cnt[idx]; }
    }
    if (tid == 1023) base[N_NODES] = run;
}

// ---------------- convert: CSR slot assignment, 4 edges per thread ------------
__global__ __launch_bounds__(256)
void convert_kernel(const void* __restrict__ eidx,
                    const int* __restrict__ base, int* __restrict__ cnt,
                    int* __restrict__ psrc, int* __restrict__ pdst,
                    int* __restrict__ pinv) {
    const int i0 = blockIdx.x * blockDim.x + threadIdx.x;
    if (i0 >= CVT_T) return;              // R11 bugfix: padded threads duplicated edges
    const bool idx64 = (g_idx64 != 0);
    int s[4], d[4];
#pragma unroll
    for (int u = 0; u < 4; u++) {
        const int e = i0 + u * CVT_T;
        if (e < N_EDGES) {
            if (idx64) {
                s[u] = (int)__ldg((const long long*)eidx + e);
                d[u] = (int)__ldg((const long long*)eidx + (size_t)N_EDGES + e);
            } else {
                s[u] = __ldg((const int*)eidx + e);
                d[u] = __ldg((const int*)eidx + N_EDGES + e);
            }
        } else d[u] = -1;
    }
    int pp[4];
#pragma unroll
    for (int u = 0; u < 4; u++)
        if (d[u] >= 0) pp[u] = base[d[u]] + atomicAdd(&cnt[d[u]], 1);
#pragma unroll
    for (int u = 0; u < 4; u++) {
        if (d[u] >= 0) {
            psrc[pp[u]] = s[u];
            pdst[pp[u]] = d[u];
            pinv[pp[u]] = i0 + u * CVT_T;
        }
    }
}

// ---------------- node projections: 3 GEMMs in one launch (gridDim.y) ---------
#define BM 64
#define BK 16

__global__ __launch_bounds__(256)
void sgemm3_kernel(const float* __restrict__ A,
                   const float* __restrict__ WQ, const float* __restrict__ WK,
                   const float* __restrict__ WV,
                   float* __restrict__ Q, float* __restrict__ K,
                   float* __restrict__ V, int M) {
    const float* W = (blockIdx.y == 0) ? WQ : (blockIdx.y == 1) ? WK : WV;
    float*       C = (blockIdx.y == 0) ? Q  : (blockIdx.y == 1) ? K  : V;

    __shared__ float As[BK][BM + 1];
    __shared__ float Ws[BK][DIM];

    const int tid = threadIdx.x;
    const int tx = tid & 31;
    const int ty = tid >> 5;
    const int m0 = blockIdx.x * BM;

    float acc[8][4];
#pragma unroll
    for (int i = 0; i < 8; i++)
#pragma unroll
        for (int j = 0; j < 4; j++) acc[i][j] = 0.0f;

    for (int k0 = 0; k0 < DIM; k0 += BK) {
        {
            const int r = tid >> 2;
            const int c = (tid & 3) * 4;
            const int gr = m0 + r;
            float4 a = make_float4(0.f, 0.f, 0.f, 0.f);
            if (gr < M) a = *(const float4*)(A + (size_t)gr * DIM + k0 + c);
            As[c + 0][r] = a.x;
            As[c + 1][r] = a.y;
            As[c + 2][r] = a.z;
            As[c + 3][r] = a.w;
        }
        {
            const int cw = (tid & 31) * 4;
            const int rw = tid >> 5;
            *(float4*)&Ws[rw][cw]     = *(const float4*)(W + (size_t)(k0 + rw) * DIM + cw);
            *(float4*)&Ws[rw + 8][cw] = *(const float4*)(W + (size_t)(k0 + rw + 8) * DIM + cw);
        }
        __syncthreads();

#pragma unroll
        for (int kk = 0; kk < BK; kk++) {
            float a[8];
#pragma unroll
            for (int i = 0; i < 8; i++) a[i] = As[kk][ty * 8 + i];
            const float4 wv = *(const float4*)&Ws[kk][tx * 4];
#pragma unroll
            for (int i = 0; i < 8; i++) {
                acc[i][0] = fmaf(a[i], wv.x, acc[i][0]);
                acc[i][1] = fmaf(a[i], wv.y, acc[i][1]);
                acc[i][2] = fmaf(a[i], wv.z, acc[i][2]);
                acc[i][3] = fmaf(a[i], wv.w, acc[i][3]);
            }
        }
        __syncthreads();
    }

#pragma unroll
    for (int i = 0; i < 8; i++) {
        const int gr = m0 + ty * 8 + i;
        if (gr < M) {
            *(float4*)(C + (size_t)gr * DIM + tx * 4) =
                make_float4(acc[i][0], acc[i][1], acc[i][2], acc[i][3]);
        }
    }
}

// ---------------- fp16 helpers -------------------------------------------------
__device__ __forceinline__ uint32_t f2h2(float lo, float hi) {
    __half2 h = __floats2half2_rn(lo, hi);
    return *(uint32_t*)&h;
}

__device__ __forceinline__ void mma_f16(float* d, const uint32_t* a, const uint32_t* b) {
    asm volatile(
        "mma.sync.aligned.m16n8k16.row.col.f32.f16.f16.f32 "
        "{%0,%1,%2,%3}, {%4,%5,%6,%7}, {%8,%9}, {%0,%1,%2,%3};"
        : "+f"(d[0]), "+f"(d[1]), "+f"(d[2]), "+f"(d[3])
        : "r"(a[0]), "r"(a[1]), "r"(a[2]), "r"(a[3]),
          "r"(b[0]), "r"(b[1]));
}

// ---------------- fused edge kernel: persistent, prefetch-pipelined, fp16 -----
// Grid = 304 persistent CTAs (2/SM). Each CTA: load WE once as half2 into SMEM;
// per tile of 64 slots: STS prefetched ea rows (half2) -> fp16 m16n8k16 GEMM
// (prefetching next tile's ea rows) -> Eh (fp32) to SMEM -> score epilogue.
// Only the Eh FACTOR goes through fp16; K/Q stay fp32.
__global__ __launch_bounds__(256, 2)
void fused_edge_kernel(const float* __restrict__ ea,
                       const float* __restrict__ WE,
                       const float* __restrict__ Q,
                       const float* __restrict__ K,
                       const int* __restrict__ psrc,
                       const int* __restrict__ pdst,
                       const int* __restrict__ pinv,
                       float* __restrict__ pscore) {
    extern __shared__ uint32_t smem[];
    uint32_t* B2 = smem;                         // [64][PADB] half2
    uint32_t* A2 = B2 + 64 * PADB;               // [64][PADA] half2
    float*    Eh = (float*)(A2 + 64 * PADA);     // [64][PAD]  fp32

    const int tid  = threadIdx.x;
    const int lane = tid & 31;
    const int w    = tid >> 5;                   // 0..7

    // ---- load WE (128x128) into SMEM as half2 along k — ONCE per CTA ----
    for (int idx = tid; idx < 64 * DIM; idx += 256) {
        const int kk = idx >> 7;
        const int n  = idx & 127;
        const float w0 = __ldg(WE + (size_t)(2 * kk) * DIM + n);
        const float w1 = __ldg(WE + (size_t)(2 * kk + 1) * DIM + n);
        B2[kk * PADB + n] = f2h2(w0, w1);
    }

    const int cnt = 82 + (blockIdx.x < (NTILES - NPER * 82) ? 1 : 0);

    // ---- register prefetch of one A tile (warp w owns rows w, w+8, .., w+56)
    float4 areg[8];
    auto prefetchA = [&](int tile) {
        const int e0 = tile * TILE_E;
        int myp = 0;
        if (lane < 8) myp = __ldg(pinv + e0 + w + 8 * lane);
#pragma unroll
        for (int i = 0; i < 8; i++) {
            const int eid = __shfl_sync(0xffffffffu, myp, i);
            areg[i] = __ldg((const float4*)(ea + (size_t)eid * DIM) + lane);
        }
    };

    prefetchA(blockIdx.x);   // prologue

    const int g  = lane >> 2;
    const int cc = lane & 3;
    const int mb = (w & 1) * 32;
    const int nb = (w >> 1) * 32;

    for (int j = 0; j < cnt; j++) {
        const int tile = blockIdx.x + j * NPER;
        const int e0   = tile * TILE_E;

        __syncthreads();   // previous epilogue done reading Eh

        // ---- STS prefetched rows as half2 (k pairs) ----
#pragma unroll
        for (int i = 0; i < 8; i++) {
            const int r = w + 8 * i;
            A2[r * PADA + lane * 2]     = f2h2(areg[i].x, areg[i].y);
            A2[r * PADA + lane * 2 + 1] = f2h2(areg[i].z, areg[i].w);
        }
        __syncthreads();

        // ---- prefetch next tile's A rows (LDGs hide under the GEMM below) ----
        if (j + 1 < cnt) prefetchA(blockIdx.x + (j + 1) * NPER);

        // ---- GEMM: 8 warps, each 32 slots x 32 cols, fp16 m16n8k16 ----
        float acc[2][4][4];
#pragma unroll
        for (int mt = 0; mt < 2; mt++)
#pragma unroll
            for (int nt = 0; nt < 4; nt++)
#pragma unroll
                for (int q = 0; q < 4; q++) acc[mt][nt][q] = 0.0f;

#pragma unroll
        for (int ks = 0; ks < 8; ks++) {
            const int kk = 8 * ks + cc;            // half2 index along k
            uint32_t a[2][4];
#pragma unroll
            for (int mt = 0; mt < 2; mt++) {
                const int r = mb + 16 * mt + g;
                a[mt][0] = A2[r * PADA + kk];
                a[mt][1] = A2[(r + 8) * PADA + kk];
                a[mt][2] = A2[r * PADA + kk + 4];
                a[mt][3] = A2[(r + 8) * PADA + kk + 4];
            }
            uint32_t b[4][2];
#pragma unroll
            for (int nt = 0; nt < 4; nt++) {
                const int n = nb + 8 * nt + g;
                b[nt][0] = B2[kk * PADB + n];
                b[nt][1] = B2[(kk + 4) * PADB + n];
            }
#pragma unroll
            for (int mt = 0; mt < 2; mt++)
#pragma unroll
                for (int nt = 0; nt < 4; nt++)
                    mma_f16(acc[mt][nt], a[mt], b[nt]);
        }
        __syncthreads();

        // ---- write Eh tile (fp32) ----
#pragma unroll
        for (int mt = 0; mt < 2; mt++) {
#pragma unroll
            for (int nt = 0; nt < 4; nt++) {
                const int r   = mb + 16 * mt + g;
                const int col = nb + 8 * nt + 2 * cc;
                *(float2*)&Eh[r * PAD + col] =
                    make_float2(acc[mt][nt][0], acc[mt][nt][1]);
                *(float2*)&Eh[(r + 8) * PAD + col] =
                    make_float2(acc[mt][nt][2], acc[mt][nt][3]);
            }
        }
        __syncthreads();

        // ---- score + sequential slot write: warp w handles slots 8w..8w+7 ----
#pragma unroll 1
        for (int b0 = 0; b0 < 8; b0 += 4) {
            float4 ehv[4], kv[4], qv[4];
#pragma unroll
            for (int jj = 0; jj < 4; jj++) {
                const int el   = w * 8 + b0 + jj;
                const int slot = e0 + el;
                const int src = __ldg(psrc + slot);
                const int dst = __ldg(pdst + slot);
                ehv[jj] = *(const float4*)&Eh[el * PAD + 4 * lane];
                kv[jj]  = __ldg((const float4*)(K + (size_t)src * DIM) + lane);
                qv[jj]  = __ldg((const float4*)(Q + (size_t)dst * DIM) + lane);
            }
#pragma unroll
            for (int jj = 0; jj < 4; jj++) {
                float s = ehv[jj].x * kv[jj].x * qv[jj].x +
                          ehv[jj].y * kv[jj].y * qv[jj].y +
                          ehv[jj].z * kv[jj].z * qv[jj].z +
                          ehv[jj].w * kv[jj].w * qv[jj].w;
                s += __shfl_xor_sync(0xffffffffu, s, 1);
                s += __shfl_xor_sync(0xffffffffu, s, 2);
                s *= 0.25f;
                s = expf(fminf(fmaxf(s, -5.0f), 5.0f));
                if ((lane & 3) == 0)
                    pscore[(size_t)(e0 + w * 8 + b0 + jj) * NH + (lane >> 2)] = s;
            }
        }
    }
}

// ---------------- gather: one warp per node, register accumulation ------------
__global__ __launch_bounds__(256)
void gather_kernel(const int* __restrict__ base,
                   const int* __restrict__ psrc,
                   const float* __restrict__ pscore,
                   const float* __restrict__ V,
                   float* __restrict__ out) {
    const int node = (blockIdx.x * blockDim.x + threadIdx.x) >> 5;
    const int lane = threadIdx.x & 31;
    if (node >= N_NODES) return;

    const int b = base[node];
    const int e = base[node + 1];
    const int h = lane >> 2;

    float4 acc = make_float4(0.f, 0.f, 0.f, 0.f);
    float z = 0.f;

    for (int cb = b; cb < e; cb += 32) {
        const int n = min(32, e - cb);
        int mysrc = 0;
        if (cb + lane < e) mysrc = __ldg(psrc + cb + lane);

        int i = 0;
        for (; i + 8 <= n; i += 8) {
#pragma unroll
            for (int u = 0; u < 8; u++) {
                const int src = __shfl_sync(0xffffffffu, mysrc, i + u);
                const float s = __ldg(pscore + (size_t)(cb + i + u) * NH + h);
                const float4 v = __ldg((const float4*)(V + (size_t)src * DIM) + lane);
                acc.x = fmaf(v.x, s, acc.x);
                acc.y = fmaf(v.y, s, acc.y);
                acc.z = fmaf(v.z, s, acc.z);
                acc.w = fmaf(v.w, s, acc.w);
                z += s;
            }
        }
        for (; i < n; i++) {
            const int src = __shfl_sync(0xffffffffu, mysrc, i);
            const float s = __ldg(pscore + (size_t)(cb + i) * NH + h);
            const float4 v = __ldg((const float4*)(V + (size_t)src * DIM) + lane);
            acc.x = fmaf(v.x, s, acc.x);
            acc.y = fmaf(v.y, s, acc.y);
            acc.z = fmaf(v.z, s, acc.z);
            acc.w = fmaf(v.w, s, acc.w);
            z += s;
        }
    }
    const float inv = 1.0f / (z + 1e-6f);
    *(float4*)(out + (size_t)node * DIM + lane * 4) =
        make_float4(acc.x * inv, acc.y * inv, acc.z * inv, acc.w * inv);
}

// ---------------- launch --------------------------------------------------------
extern "C" void kernel_launch(void* const* d_in, const int* in_sizes, int n_in,
                              void* d_out, int out_size) {
    const float* h   = (const float*)d_in[0];
    const float* ea  = (const float*)d_in[1];
    const float* WQ  = (const float*)d_in[2];
    const float* WK  = (const float*)d_in[3];
    const float* WV  = (const float*)d_in[4];
    const float* WE  = (const float*)d_in[5];
    const void*  eix = d_in[6];
    float* out = (float*)d_out;

    void *qp, *kp, *vp, *cntp, *basep, *psrcp, *pdstp, *pinvp, *pscorep;
    cudaGetSymbolAddress(&qp,      g_Q);
    cudaGetSymbolAddress(&kp,      g_K);
    cudaGetSymbolAddress(&vp,      g_V);
    cudaGetSymbolAddress(&cntp,    g_cnt);
    cudaGetSymbolAddress(&basep,   g_base);
    cudaGetSymbolAddress(&psrcp,   g_psrc);
    cudaGetSymbolAddress(&pdstp,   g_pdst);
    cudaGetSymbolAddress(&pinvp,   g_pinv);
    cudaGetSymbolAddress(&pscorep, g_pscore);

    detect_idx_kernel<<<1, 1>>>(eix);

    // CSR build (4 edges/thread for atomic-latency hiding)
    cudaMemsetAsync(cntp, 0, N_NODES * sizeof(int));
    hist_kernel<<<(CVT_T + 255) / 256, 256>>>(eix, (int*)cntp);
    scan_kernel<<<1, 1024>>>((const int*)cntp, (int*)basep);
    cudaMemsetAsync(cntp, 0, N_NODES * sizeof(int));
    convert_kernel<<<(CVT_T + 255) / 256, 256>>>(
        eix, (const int*)basep, (int*)cntp,
        (int*)psrcp, (int*)pdstp, (int*)pinvp);

    // node projections (3 GEMMs in one launch, fp32)
    dim3 gN((N_NODES + BM - 1) / BM, 3);
    sgemm3_kernel<<<gN, 256>>>(h, WQ, WK, WV, (float*)qp, (float*)kp,
                               (float*)vp, N_NODES);

    // fused persistent fp16 edge GEMM + score (2 CTAs/SM)
    const int smem_bytes = (64 * PADB + 64 * PADA + 64 * PAD) * 4;   // 86016
    cudaFuncSetAttribute(fused_edge_kernel,
                         cudaFuncAttributeMaxDynamicSharedMemorySize, smem_bytes);
    fused_edge_kernel<<<NPER, 256, smem_bytes>>>(
        ea, WE, (const float*)qp, (const float*)kp,
        (const int*)psrcp, (const int*)pdstp, (const int*)pinvp,
        (float*)pscorep);

    // gather + normalize (one warp per node)
    gather_kernel<<<(N_NODES * 32 + 255) / 256, 256>>>(
        (const int*)basep, (const int*)psrcp, (const float*)pscorep,
        (const float*)vp, out);
}

// round 13
// speedup vs baseline: 1.0710x; 1.0710x over previous
#include <cuda_runtime.h>
#include <cuda_fp16.h>
#include <cstdint>

#define N_NODES 50000
#define N_EDGES 1600000
#define DIM 128
#define NH 8
#define TILE_E 64
#define NTILES (N_EDGES / TILE_E)   // 25000
#define NPER 304                    // persistent CTAs (2 per SM x 152 SMs)
#define PADA 68                     // A tile row stride (half2 units)
#define PADB 136                    // B tile row stride (half2 units)

// ---------------- scratch (static device globals: no alloc allowed) ----------
__device__ float g_Q[(size_t)N_NODES * DIM];
__device__ float g_K[(size_t)N_NODES * DIM];
__device__ float g_V[(size_t)N_NODES * DIM];
__device__ int   g_cnt[N_NODES];
__device__ int   g_base[N_NODES + 1];
__device__ int   g_psrc[N_EDGES];     // slot -> src node
__device__ int   g_pdst[N_EDGES];     // slot -> dst node
__device__ int   g_pinv[N_EDGES];     // slot -> original edge id
__device__ float g_pscore[(size_t)N_EDGES * NH];   // 51 MB
__device__ int   g_idx64;

// ---------------- edge_index dtype detection (int64 vs int32) ----------------
__global__ void detect_idx_kernel(const void* idx) {
    const long long* p = (const long long*)idx;
    int is64 = 1;
    for (int i = 0; i < 64; i++) {
        long long v = p[i];
        if (v < 0 || v >= N_NODES) { is64 = 0; break; }
    }
    g_idx64 = is64;
}

// ---------------- histogram of dst (simple, measured-best) --------------------
__global__ __launch_bounds__(256)
void hist_kernel(const void* __restrict__ eidx, int* __restrict__ cnt) {
    const int i = blockIdx.x * blockDim.x + threadIdx.x;
    if (i >= N_EDGES) return;
    int dst;
    if (g_idx64) dst = (int)((const long long*)eidx)[(size_t)N_EDGES + i];
    else         dst = ((const int*)eidx)[N_EDGES + i];
    atomicAdd(&cnt[dst], 1);
}

// ---------------- single-block exclusive scan (1024 threads) ------------------
__global__ __launch_bounds__(1024)
void scan_kernel(const int* __restrict__ cnt, int* __restrict__ base) {
    __shared__ int wsum[32];
    const int tid = threadIdx.x;
    const int lane = tid & 31, wid = tid >> 5;
    const int CH = (N_NODES + 1023) / 1024;   // 49
    const int start = tid * CH;

    int s = 0;
    for (int i = 0; i < CH; i++) {
        const int idx = start + i;
        if (idx < N_NODES) s += cnt[idx];
    }
    int v = s;
#pragma unroll
    for (int d = 1; d < 32; d <<= 1) {
        int n = __shfl_up_sync(0xffffffffu, v, d);
        if (lane >= d) v += n;
    }
    if (lane == 31) wsum[wid] = v;
    __syncthreads();
    if (wid == 0) {
        int wv = wsum[lane];
#pragma unroll
        for (int d = 1; d < 32; d <<= 1) {
            int n = __shfl_up_sync(0xffffffffu, wv, d);
            if (lane >= d) wv += n;
        }
        wsum[lane] = wv;
    }
    __syncthreads();
    int run = v - s + (wid > 0 ? wsum[wid - 1] : 0);
    for (int i = 0; i < CH; i++) {
        const int idx = start + i;
        if (idx < N_NODES) { base[idx] = run; run += cnt[idx]; }
    }
    if (tid == 1023) base[N_NODES] = run;
}

// ---------------- convert: CSR slot assignment (simple, measured-best) --------
__global__ __launch_bounds__(256)
void convert_kernel(const void* __restrict__ eidx,
                    const int* __restrict__ base, int* __restrict__ cnt,
                    int* __restrict__ psrc, int* __restrict__ pdst,
                    int* __restrict__ pinv) {
    const int i = blockIdx.x * blockDim.x + threadIdx.x;
    if (i >= N_EDGES) return;
    int s, d;
    if (g_idx64) {
        const long long* p = (const long long*)eidx;
        s = (int)p[i];
        d = (int)p[(size_t)N_EDGES + i];
    } else {
        const int* p = (const int*)eidx;
        s = p[i];
        d = p[N_EDGES + i];
    }
    const int pp = base[d] + atomicAdd(&cnt[d], 1);
    psrc[pp] = s;
    pdst[pp] = d;
    pinv[pp] = i;
}

// ---------------- node projections: 3 GEMMs in one launch (gridDim.y) ---------
#define BM 64
#define BK 16

__global__ __launch_bounds__(256)
void sgemm3_kernel(const float* __restrict__ A,
                   const float* __restrict__ WQ, const float* __restrict__ WK,
                   const float* __restrict__ WV,
                   float* __restrict__ Q, float* __restrict__ K,
                   float* __restrict__ V, int M) {
    const float* W = (blockIdx.y == 0) ? WQ : (blockIdx.y == 1) ? WK : WV;
    float*       C = (blockIdx.y == 0) ? Q  : (blockIdx.y == 1) ? K  : V;

    __shared__ float As[BK][BM + 1];
    __shared__ float Ws[BK][DIM];

    const int tid = threadIdx.x;
    const int tx = tid & 31;
    const int ty = tid >> 5;
    const int m0 = blockIdx.x * BM;

    float acc[8][4];
#pragma unroll
    for (int i = 0; i < 8; i++)
#pragma unroll
        for (int j = 0; j < 4; j++) acc[i][j] = 0.0f;

    for (int k0 = 0; k0 < DIM; k0 += BK) {
        {
            const int r = tid >> 2;
            const int c = (tid & 3) * 4;
            const int gr = m0 + r;
            float4 a = make_float4(0.f, 0.f, 0.f, 0.f);
            if (gr < M) a = *(const float4*)(A + (size_t)gr * DIM + k0 + c);
            As[c + 0][r] = a.x;
            As[c + 1][r] = a.y;
            As[c + 2][r] = a.z;
            As[c + 3][r] = a.w;
        }
        {
            const int cw = (tid & 31) * 4;
            const int rw = tid >> 5;
            *(float4*)&Ws[rw][cw]     = *(const float4*)(W + (size_t)(k0 + rw) * DIM + cw);
            *(float4*)&Ws[rw + 8][cw] = *(const float4*)(W + (size_t)(k0 + rw + 8) * DIM + cw);
        }
        __syncthreads();

#pragma unroll
        for (int kk = 0; kk < BK; kk++) {
            float a[8];
#pragma unroll
            for (int i = 0; i < 8; i++) a[i] = As[kk][ty * 8 + i];
            const float4 wv = *(const float4*)&Ws[kk][tx * 4];
#pragma unroll
            for (int i = 0; i < 8; i++) {
                acc[i][0] = fmaf(a[i], wv.x, acc[i][0]);
                acc[i][1] = fmaf(a[i], wv.y, acc[i][1]);
                acc[i][2] = fmaf(a[i], wv.z, acc[i][2]);
                acc[i][3] = fmaf(a[i], wv.w, acc[i][3]);
            }
        }
        __syncthreads();
    }

#pragma unroll
    for (int i = 0; i < 8; i++) {
        const int gr = m0 + ty * 8 + i;
        if (gr < M) {
            *(float4*)(C + (size_t)gr * DIM + tx * 4) =
                make_float4(acc[i][0], acc[i][1], acc[i][2], acc[i][3]);
        }
    }
}

// ---------------- fp16 helpers -------------------------------------------------
__device__ __forceinline__ uint32_t f2h2(float lo, float hi) {
    __half2 h = __floats2half2_rn(lo, hi);
    return *(uint32_t*)&h;
}

__device__ __forceinline__ void mma_f16(float* d, const uint32_t* a, const uint32_t* b) {
    asm volatile(
        "mma.sync.aligned.m16n8k16.row.col.f32.f16.f16.f32 "
        "{%0,%1,%2,%3}, {%4,%5,%6,%7}, {%8,%9}, {%0,%1,%2,%3};"
        : "+f"(d[0]), "+f"(d[1]), "+f"(d[2]), "+f"(d[3])
        : "r"(a[0]), "r"(a[1]), "r"(a[2]), "r"(a[3]),
          "r"(b[0]), "r"(b[1]));
}

// ---------------- fused edge kernel: accumulator-resident epilogue ------------
// Warp w owns 16 edges ((w&3)*16..+15) x 64 cols ((w>>2)*64..+63) = 4 complete
// heads. Scores are computed DIRECTLY from mma accumulators: no Eh SMEM buffer,
// A double-buffered, ONE __syncthreads per tile.
//   D-frag layout (m16n8k16): lane l -> rows g=(l>>2), g+8; cols 2*(l&3)+{0,1}
//   within each 8-col nt block. Head of nt block = nt>>1 (local), +4*(w>>2) global.
__global__ __launch_bounds__(256, 2)
void fused_edge_kernel(const float* __restrict__ ea,
                       const float* __restrict__ WE,
                       const float* __restrict__ Q,
                       const float* __restrict__ K,
                       const int* __restrict__ psrc,
                       const int* __restrict__ pdst,
                       const int* __restrict__ pinv,
                       float* __restrict__ pscore) {
    extern __shared__ uint32_t smem[];
    uint32_t* B2 = smem;                         // [64][PADB] half2 (WE, k-paired)
    uint32_t* A2b[2];
    A2b[0] = B2 + 64 * PADB;                     // [64][PADA] half2, buffer 0
    A2b[1] = A2b[0] + 64 * PADA;                 // buffer 1

    const int tid  = threadIdx.x;
    const int lane = tid & 31;
    const int w    = tid >> 5;                   // 0..7

    // ---- load WE (128x128) into SMEM as half2 along k — ONCE per CTA ----
    for (int idx = tid; idx < 64 * DIM; idx += 256) {
        const int kk = idx >> 7;
        const int n  = idx & 127;
        const float w0 = __ldg(WE + (size_t)(2 * kk) * DIM + n);
        const float w1 = __ldg(WE + (size_t)(2 * kk + 1) * DIM + n);
        B2[kk * PADB + n] = f2h2(w0, w1);
    }

    const int cnt = 82 + (blockIdx.x < (NTILES - NPER * 82) ? 1 : 0);

    // ---- register prefetch of one A tile (warp w owns rows w, w+8, .., w+56)
    float4 areg[8];
    auto prefetchA = [&](int tile) {
        const int e0 = tile * TILE_E;
        int myp = 0;
        if (lane < 8) myp = __ldg(pinv + e0 + w + 8 * lane);
#pragma unroll
        for (int i = 0; i < 8; i++) {
            const int eid = __shfl_sync(0xffffffffu, myp, i);
            areg[i] = __ldg((const float4*)(ea + (size_t)eid * DIM) + lane);
        }
    };

    prefetchA(blockIdx.x);   // prologue

    const int g  = lane >> 2;
    const int cc = lane & 3;
    const int mb = (w & 3) * 16;    // 16-edge block
    const int nb = (w >> 2) * 64;   // 64-col block (4 heads)
    const int hbase = (w >> 2) * 4; // global head base

    for (int j = 0; j < cnt; j++) {
        const int tile = blockIdx.x + j * NPER;
        const int e0   = tile * TILE_E;
        uint32_t* A2 = A2b[j & 1];

        // ---- STS prefetched rows as half2 (safe: all warps passed sync(j-1),
        //      so every GEMM(j-2) read of this buffer is complete) ----
#pragma unroll
        for (int i = 0; i < 8; i++) {
            const int r = w + 8 * i;
            A2[r * PADA + lane * 2]     = f2h2(areg[i].x, areg[i].y);
            A2[r * PADA + lane * 2 + 1] = f2h2(areg[i].z, areg[i].w);
        }
        // ---- prefetch next tile's A rows (hidden under GEMM below) ----
        if (j + 1 < cnt) prefetchA(blockIdx.x + (j + 1) * NPER);

        // ---- edge indices for this warp's 16 edges (coalesced) ----
        int idxreg;
        if (lane < 16) idxreg = __ldg(psrc + e0 + mb + lane);
        else           idxreg = __ldg(pdst + e0 + mb + (lane - 16));

        __syncthreads();   // A(j) visible to all warps

        // ---- GEMM: 16 edges x 64 cols, fp16 m16n8k16 ----
        float acc[8][4];
#pragma unroll
        for (int nt = 0; nt < 8; nt++)
#pragma unroll
            for (int q = 0; q < 4; q++) acc[nt][q] = 0.0f;

#pragma unroll
        for (int ks = 0; ks < 8; ks++) {
            const int kk = 8 * ks + cc;            // half2 index along k
            uint32_t a[4];
            a[0] = A2[(mb + g) * PADA + kk];
            a[1] = A2[(mb + g + 8) * PADA + kk];
            a[2] = A2[(mb + g) * PADA + kk + 4];
            a[3] = A2[(mb + g + 8) * PADA + kk + 4];
            uint32_t b[8][2];
#pragma unroll
            for (int nt = 0; nt < 8; nt++) {
                const int n = nb + 8 * nt + g;
                b[nt][0] = B2[kk * PADB + n];
                b[nt][1] = B2[(kk + 4) * PADB + n];
            }
#pragma unroll
            for (int nt = 0; nt < 8; nt++)
                mma_f16(acc[nt], a, b[nt]);
        }

        // ---- score epilogue straight from accumulators (no sync, no SMEM) ----
#pragma unroll
        for (int half = 0; half < 2; half++) {
            const int er  = g + 8 * half;              // local edge 0..15
            const int src = __shfl_sync(0xffffffffu, idxreg, er);
            const int dst = __shfl_sync(0xffffffffu, idxreg, 16 + er);
            const float* Kp = K + (size_t)src * DIM;
            const float* Qp = Q + (size_t)dst * DIM;

            float hsum[4] = {0.f, 0.f, 0.f, 0.f};
#pragma unroll
            for (int chunk = 0; chunk < 2; chunk++) {
                float2 k2[4], q2[4];
#pragma unroll
                for (int t = 0; t < 4; t++) {
                    const int col = nb + 8 * (4 * chunk + t) + 2 * cc;
                    k2[t] = __ldg((const float2*)(Kp + col));
                    q2[t] = __ldg((const float2*)(Qp + col));
                }
#pragma unroll
                for (int t = 0; t < 4; t++) {
                    const int nt = 4 * chunk + t;
                    hsum[nt >> 1] += acc[nt][2 * half]     * k2[t].x * q2[t].x
                                   + acc[nt][2 * half + 1] * k2[t].y * q2[t].y;
                }
            }
            // all-reduce over the 4 lanes of this row group
#pragma unroll
            for (int h = 0; h < 4; h++) {
                hsum[h] += __shfl_xor_sync(0xffffffffu, hsum[h], 1);
                hsum[h] += __shfl_xor_sync(0xffffffffu, hsum[h], 2);
            }
            float s = 0.25f * hsum[cc];
            s = expf(fminf(fmaxf(s, -5.0f), 5.0f));
            pscore[(size_t)(e0 + mb + er) * NH + hbase + cc] = s;
        }
    }
}

// ---------------- gather: one warp per node, register accumulation ------------
__global__ __launch_bounds__(256)
void gather_kernel(const int* __restrict__ base,
                   const int* __restrict__ psrc,
                   const float* __restrict__ pscore,
                   const float* __restrict__ V,
                   float* __restrict__ out) {
    const int node = (blockIdx.x * blockDim.x + threadIdx.x) >> 5;
    const int lane = threadIdx.x & 31;
    if (node >= N_NODES) return;

    const int b = base[node];
    const int e = base[node + 1];
    const int h = lane >> 2;

    float4 acc = make_float4(0.f, 0.f, 0.f, 0.f);
    float z = 0.f;

    for (int cb = b; cb < e; cb += 32) {
        const int n = min(32, e - cb);
        int mysrc = 0;
        if (cb + lane < e) mysrc = __ldg(psrc + cb + lane);

        int i = 0;
        for (; i + 8 <= n; i += 8) {
#pragma unroll
            for (int u = 0; u < 8; u++) {
                const int src = __shfl_sync(0xffffffffu, mysrc, i + u);
                const float s = __ldg(pscore + (size_t)(cb + i + u) * NH + h);
                const float4 v = __ldg((const float4*)(V + (size_t)src * DIM) + lane);
                acc.x = fmaf(v.x, s, acc.x);
                acc.y = fmaf(v.y, s, acc.y);
                acc.z = fmaf(v.z, s, acc.z);
                acc.w = fmaf(v.w, s, acc.w);
                z += s;
            }
        }
        for (; i < n; i++) {
            const int src = __shfl_sync(0xffffffffu, mysrc, i);
            const float s = __ldg(pscore + (size_t)(cb + i) * NH + h);
            const float4 v = __ldg((const float4*)(V + (size_t)src * DIM) + lane);
            acc.x = fmaf(v.x, s, acc.x);
            acc.y = fmaf(v.y, s, acc.y);
            acc.z = fmaf(v.z, s, acc.z);
            acc.w = fmaf(v.w, s, acc.w);
            z += s;
        }
    }
    const float inv = 1.0f / (z + 1e-6f);
    *(float4*)(out + (size_t)node * DIM + lane * 4) =
        make_float4(acc.x * inv, acc.y * inv, acc.z * inv, acc.w * inv);
}

// ---------------- launch --------------------------------------------------------
extern "C" void kernel_launch(void* const* d_in, const int* in_sizes, int n_in,
                              void* d_out, int out_size) {
    const float* h   = (const float*)d_in[0];
    const float* ea  = (const float*)d_in[1];
    const float* WQ  = (const float*)d_in[2];
    const float* WK  = (const float*)d_in[3];
    const float* WV  = (const float*)d_in[4];
    const float* WE  = (const float*)d_in[5];
    const void*  eix = d_in[6];
    float* out = (float*)d_out;

    void *qp, *kp, *vp, *cntp, *basep, *psrcp, *pdstp, *pinvp, *pscorep;
    cudaGetSymbolAddress(&qp,      g_Q);
    cudaGetSymbolAddress(&kp,      g_K);
    cudaGetSymbolAddress(&vp,      g_V);
    cudaGetSymbolAddress(&cntp,    g_cnt);
    cudaGetSymbolAddress(&basep,   g_base);
    cudaGetSymbolAddress(&psrcp,   g_psrc);
    cudaGetSymbolAddress(&pdstp,   g_pdst);
    cudaGetSymbolAddress(&pinvp,   g_pinv);
    cudaGetSymbolAddress(&pscorep, g_pscore);

    detect_idx_kernel<<<1, 1>>>(eix);

    // CSR build
    cudaMemsetAsync(cntp, 0, N_NODES * sizeof(int));
    hist_kernel<<<(N_EDGES + 255) / 256, 256>>>(eix, (int*)cntp);
    scan_kernel<<<1, 1024>>>((const int*)cntp, (int*)basep);
    cudaMemsetAsync(cntp, 0, N_NODES * sizeof(int));
    convert_kernel<<<(N_EDGES + 255) / 256, 256>>>(
        eix, (const int*)basep, (int*)cntp,
        (int*)psrcp, (int*)pdstp, (int*)pinvp);

    // node projections (3 GEMMs in one launch, fp32)
    dim3 gN((N_NODES + BM - 1) / BM, 3);
    sgemm3_kernel<<<gN, 256>>>(h, WQ, WK, WV, (float*)qp, (float*)kp,
                               (float*)vp, N_NODES);

    // fused persistent fp16 edge GEMM + accumulator-resident score (2 CTAs/SM)
    const int smem_bytes = (64 * PADB + 2 * 64 * PADA) * 4;   // 69632
    cudaFuncSetAttribute(fused_edge_kernel,
                         cudaFuncAttributeMaxDynamicSharedMemorySize, smem_bytes);
    fused_edge_kernel<<<NPER, 256, smem_bytes>>>(
        ea, WE, (const float*)qp, (const float*)kp,
        (const int*)psrcp, (const int*)pdstp, (const int*)pinvp,
        (float*)pscorep);

    // gather + normalize (one warp per node)
    gather_kernel<<<(N_NODES * 32 + 255) / 256, 256>>>(
        (const int*)basep, (const int*)psrcp, (const float*)pscorep,
        (const float*)vp, out);
}

// round 14
// speedup vs baseline: 1.1081x; 1.0347x over previous
#include <cuda_runtime.h>
#include <cuda_fp16.h>
#include <cstdint>

#define N_NODES 50000
#define N_EDGES 1600000
#define DIM 128
#define NH 8
#define TILE_E 64
#define NTILES (N_EDGES / TILE_E)   // 25000
#define NPER 304                    // persistent CTAs (2 per SM x 152 SMs)
#define PADA 68                     // A tile row stride (half2 units)
#define PADB 136                    // B tile row stride (half2 units)

// ---------------- scratch (static device globals: no alloc allowed) ----------
// Q/K/V stored fp16 (STORAGE ONLY; all math fp32). R10's fp16 failure was a
// CSR bug confound (R11 proved identical error with fp32) — first clean test.
__device__ __half g_Q[(size_t)N_NODES * DIM];
__device__ __half g_K[(size_t)N_NODES * DIM];
__device__ __half g_V[(size_t)N_NODES * DIM];
__device__ int    g_cnt[N_NODES];
__device__ int    g_base[N_NODES + 1];
__device__ int    g_psrc[N_EDGES];     // slot -> src node
__device__ int    g_pdst[N_EDGES];     // slot -> dst node
__device__ int    g_pinv[N_EDGES];     // slot -> original edge id
__device__ float  g_pscore[(size_t)N_EDGES * NH];   // 51 MB
__device__ int    g_idx64;

// ---------------- edge_index dtype detection (int64 vs int32) ----------------
__global__ void detect_idx_kernel(const void* idx) {
    const long long* p = (const long long*)idx;
    int is64 = 1;
    for (int i = 0; i < 64; i++) {
        long long v = p[i];
        if (v < 0 || v >= N_NODES) { is64 = 0; break; }
    }
    g_idx64 = is64;
}

// ---------------- histogram of dst (simple, measured-best) --------------------
__global__ __launch_bounds__(256)
void hist_kernel(const void* __restrict__ eidx, int* __restrict__ cnt) {
    const int i = blockIdx.x * blockDim.x + threadIdx.x;
    if (i >= N_EDGES) return;
    int dst;
    if (g_idx64) dst = (int)((const long long*)eidx)[(size_t)N_EDGES + i];
    else         dst = ((const int*)eidx)[N_EDGES + i];
    atomicAdd(&cnt[dst], 1);
}

// ---------------- single-block exclusive scan (1024 threads) ------------------
__global__ __launch_bounds__(1024)
void scan_kernel(const int* __restrict__ cnt, int* __restrict__ base) {
    __shared__ int wsum[32];
    const int tid = threadIdx.x;
    const int lane = tid & 31, wid = tid >> 5;
    const int CH = (N_NODES + 1023) / 1024;   // 49
    const int start = tid * CH;

    int s = 0;
    for (int i = 0; i < CH; i++) {
        const int idx = start + i;
        if (idx < N_NODES) s += cnt[idx];
    }
    int v = s;
#pragma unroll
    for (int d = 1; d < 32; d <<= 1) {
        int n = __shfl_up_sync(0xffffffffu, v, d);
        if (lane >= d) v += n;
    }
    if (lane == 31) wsum[wid] = v;
    __syncthreads();
    if (wid == 0) {
        int wv = wsum[lane];
#pragma unroll
        for (int d = 1; d < 32; d <<= 1) {
            int n = __shfl_up_sync(0xffffffffu, wv, d);
            if (lane >= d) wv += n;
        }
        wsum[lane] = wv;
    }
    __syncthreads();
    int run = v - s + (wid > 0 ? wsum[wid - 1] : 0);
    for (int i = 0; i < CH; i++) {
        const int idx = start + i;
        if (idx < N_NODES) { base[idx] = run; run += cnt[idx]; }
    }
    if (tid == 1023) base[N_NODES] = run;
}

// ---------------- convert: CSR slot assignment (simple, measured-best) --------
__global__ __launch_bounds__(256)
void convert_kernel(const void* __restrict__ eidx,
                    const int* __restrict__ base, int* __restrict__ cnt,
                    int* __restrict__ psrc, int* __restrict__ pdst,
                    int* __restrict__ pinv) {
    const int i = blockIdx.x * blockDim.x + threadIdx.x;
    if (i >= N_EDGES) return;
    int s, d;
    if (g_idx64) {
        const long long* p = (const long long*)eidx;
        s = (int)p[i];
        d = (int)p[(size_t)N_EDGES + i];
    } else {
        const int* p = (const int*)eidx;
        s = p[i];
        d = p[N_EDGES + i];
    }
    const int pp = base[d] + atomicAdd(&cnt[d], 1);
    psrc[pp] = s;
    pdst[pp] = d;
    pinv[pp] = i;
}

// ---------------- node projections: fp32 math, fp16 storage -------------------
#define BM 64
#define BK 16

__global__ __launch_bounds__(256)
void sgemm3_kernel(const float* __restrict__ A,
                   const float* __restrict__ WQ, const float* __restrict__ WK,
                   const float* __restrict__ WV,
                   __half* __restrict__ Q, __half* __restrict__ K,
                   __half* __restrict__ V, int M) {
    const float* W = (blockIdx.y == 0) ? WQ : (blockIdx.y == 1) ? WK : WV;
    __half*      C = (blockIdx.y == 0) ? Q  : (blockIdx.y == 1) ? K  : V;

    __shared__ float As[BK][BM + 1];
    __shared__ float Ws[BK][DIM];

    const int tid = threadIdx.x;
    const int tx = tid & 31;
    const int ty = tid >> 5;
    const int m0 = blockIdx.x * BM;

    float acc[8][4];
#pragma unroll
    for (int i = 0; i < 8; i++)
#pragma unroll
        for (int j = 0; j < 4; j++) acc[i][j] = 0.0f;

    for (int k0 = 0; k0 < DIM; k0 += BK) {
        {
            const int r = tid >> 2;
            const int c = (tid & 3) * 4;
            const int gr = m0 + r;
            float4 a = make_float4(0.f, 0.f, 0.f, 0.f);
            if (gr < M) a = *(const float4*)(A + (size_t)gr * DIM + k0 + c);
            As[c + 0][r] = a.x;
            As[c + 1][r] = a.y;
            As[c + 2][r] = a.z;
            As[c + 3][r] = a.w;
        }
        {
            const int cw = (tid & 31) * 4;
            const int rw = tid >> 5;
            *(float4*)&Ws[rw][cw]     = *(const float4*)(W + (size_t)(k0 + rw) * DIM + cw);
            *(float4*)&Ws[rw + 8][cw] = *(const float4*)(W + (size_t)(k0 + rw + 8) * DIM + cw);
        }
        __syncthreads();

#pragma unroll
        for (int kk = 0; kk < BK; kk++) {
            float a[8];
#pragma unroll
            for (int i = 0; i < 8; i++) a[i] = As[kk][ty * 8 + i];
            const float4 wv = *(const float4*)&Ws[kk][tx * 4];
#pragma unroll
            for (int i = 0; i < 8; i++) {
                acc[i][0] = fmaf(a[i], wv.x, acc[i][0]);
                acc[i][1] = fmaf(a[i], wv.y, acc[i][1]);
                acc[i][2] = fmaf(a[i], wv.z, acc[i][2]);
                acc[i][3] = fmaf(a[i], wv.w, acc[i][3]);
            }
        }
        __syncthreads();
    }

#pragma unroll
    for (int i = 0; i < 8; i++) {
        const int gr = m0 + ty * 8 + i;
        if (gr < M) {
            __half2 h0 = __floats2half2_rn(acc[i][0], acc[i][1]);
            __half2 h1 = __floats2half2_rn(acc[i][2], acc[i][3]);
            *(uint2*)(C + (size_t)gr * DIM + tx * 4) =
                make_uint2(*(uint32_t*)&h0, *(uint32_t*)&h1);
        }
    }
}

// ---------------- fp16 helpers -------------------------------------------------
__device__ __forceinline__ uint32_t f2h2(float lo, float hi) {
    __half2 h = __floats2half2_rn(lo, hi);
    return *(uint32_t*)&h;
}

__device__ __forceinline__ float4 h4_to_f4(uint2 raw) {
    const float2 lo = __half22float2(*(__half2*)&raw.x);
    const float2 hi = __half22float2(*(__half2*)&raw.y);
    return make_float4(lo.x, lo.y, hi.x, hi.y);
}

__device__ __forceinline__ void mma_f16(float* d, const uint32_t* a, const uint32_t* b) {
    asm volatile(
        "mma.sync.aligned.m16n8k16.row.col.f32.f16.f16.f32 "
        "{%0,%1,%2,%3}, {%4,%5,%6,%7}, {%8,%9}, {%0,%1,%2,%3};"
        : "+f"(d[0]), "+f"(d[1]), "+f"(d[2]), "+f"(d[3])
        : "r"(a[0]), "r"(a[1]), "r"(a[2]), "r"(a[3]),
          "r"(b[0]), "r"(b[1]));
}

// ---------------- fused edge kernel: accumulator-resident epilogue ------------
// Warp w owns 16 edges x 64 cols (4 heads); scores straight from accumulators.
// A double-buffered; ONE __syncthreads per tile. K/Q read as fp16 (halved L2).
__global__ __launch_bounds__(256, 2)
void fused_edge_kernel(const float* __restrict__ ea,
                       const float* __restrict__ WE,
                       const __half* __restrict__ Q,
                       const __half* __restrict__ K,
                       const int* __restrict__ psrc,
                       const int* __restrict__ pdst,
                       const int* __restrict__ pinv,
                       float* __restrict__ pscore) {
    extern __shared__ uint32_t smem[];
    uint32_t* B2 = smem;                         // [64][PADB] half2 (WE, k-paired)
    uint32_t* A2b[2];
    A2b[0] = B2 + 64 * PADB;                     // [64][PADA] half2, buffer 0
    A2b[1] = A2b[0] + 64 * PADA;                 // buffer 1

    const int tid  = threadIdx.x;
    const int lane = tid & 31;
    const int w    = tid >> 5;                   // 0..7

    // ---- load WE (128x128) into SMEM as half2 along k — ONCE per CTA ----
    for (int idx = tid; idx < 64 * DIM; idx += 256) {
        const int kk = idx >> 7;
        const int n  = idx & 127;
        const float w0 = __ldg(WE + (size_t)(2 * kk) * DIM + n);
        const float w1 = __ldg(WE + (size_t)(2 * kk + 1) * DIM + n);
        B2[kk * PADB + n] = f2h2(w0, w1);
    }

    const int cnt = 82 + (blockIdx.x < (NTILES - NPER * 82) ? 1 : 0);

    // ---- register prefetch of one A tile (warp w owns rows w, w+8, .., w+56)
    float4 areg[8];
    auto prefetchA = [&](int tile) {
        const int e0 = tile * TILE_E;
        int myp = 0;
        if (lane < 8) myp = __ldg(pinv + e0 + w + 8 * lane);
#pragma unroll
        for (int i = 0; i < 8; i++) {
            const int eid = __shfl_sync(0xffffffffu, myp, i);
            areg[i] = __ldg((const float4*)(ea + (size_t)eid * DIM) + lane);
        }
    };

    prefetchA(blockIdx.x);   // prologue

    const int g  = lane >> 2;
    const int cc = lane & 3;
    const int mb = (w & 3) * 16;    // 16-edge block
    const int nb = (w >> 2) * 64;   // 64-col block (4 heads)
    const int hbase = (w >> 2) * 4; // global head base

    for (int j = 0; j < cnt; j++) {
        const int tile = blockIdx.x + j * NPER;
        const int e0   = tile * TILE_E;
        uint32_t* A2 = A2b[j & 1];

        // ---- STS prefetched rows as half2 ----
#pragma unroll
        for (int i = 0; i < 8; i++) {
            const int r = w + 8 * i;
            A2[r * PADA + lane * 2]     = f2h2(areg[i].x, areg[i].y);
            A2[r * PADA + lane * 2 + 1] = f2h2(areg[i].z, areg[i].w);
        }
        // ---- prefetch next tile's A rows (hidden under GEMM below) ----
        if (j + 1 < cnt) prefetchA(blockIdx.x + (j + 1) * NPER);

        // ---- edge indices for this warp's 16 edges (coalesced) ----
        int idxreg;
        if (lane < 16) idxreg = __ldg(psrc + e0 + mb + lane);
        else           idxreg = __ldg(pdst + e0 + mb + (lane - 16));

        __syncthreads();   // A(j) visible to all warps

        // ---- GEMM: 16 edges x 64 cols, fp16 m16n8k16 ----
        float acc[8][4];
#pragma unroll
        for (int nt = 0; nt < 8; nt++)
#pragma unroll
            for (int q = 0; q < 4; q++) acc[nt][q] = 0.0f;

#pragma unroll
        for (int ks = 0; ks < 8; ks++) {
            const int kk = 8 * ks + cc;            // half2 index along k
            uint32_t a[4];
            a[0] = A2[(mb + g) * PADA + kk];
            a[1] = A2[(mb + g + 8) * PADA + kk];
            a[2] = A2[(mb + g) * PADA + kk + 4];
            a[3] = A2[(mb + g + 8) * PADA + kk + 4];
            uint32_t b[8][2];
#pragma unroll
            for (int nt = 0; nt < 8; nt++) {
                const int n = nb + 8 * nt + g;
                b[nt][0] = B2[kk * PADB + n];
                b[nt][1] = B2[(kk + 4) * PADB + n];
            }
#pragma unroll
            for (int nt = 0; nt < 8; nt++)
                mma_f16(acc[nt], a, b[nt]);
        }

        // ---- score epilogue straight from accumulators (fp16 K/Q loads) ----
#pragma unroll
        for (int half = 0; half < 2; half++) {
            const int er  = g + 8 * half;              // local edge 0..15
            const int src = __shfl_sync(0xffffffffu, idxreg, er);
            const int dst = __shfl_sync(0xffffffffu, idxreg, 16 + er);
            const __half* Kp = K + (size_t)src * DIM;
            const __half* Qp = Q + (size_t)dst * DIM;

            float hsum[4] = {0.f, 0.f, 0.f, 0.f};
#pragma unroll
            for (int chunk = 0; chunk < 2; chunk++) {
                float2 k2[4], q2[4];
#pragma unroll
                for (int t = 0; t < 4; t++) {
                    const int col = nb + 8 * (4 * chunk + t) + 2 * cc;
                    k2[t] = __half22float2(__ldg((const __half2*)(Kp + col)));
                    q2[t] = __half22float2(__ldg((const __half2*)(Qp + col)));
                }
#pragma unroll
                for (int t = 0; t < 4; t++) {
                    const int nt = 4 * chunk + t;
                    hsum[nt >> 1] += acc[nt][2 * half]     * k2[t].x * q2[t].x
                                   + acc[nt][2 * half + 1] * k2[t].y * q2[t].y;
                }
            }
#pragma unroll
            for (int h = 0; h < 4; h++) {
                hsum[h] += __shfl_xor_sync(0xffffffffu, hsum[h], 1);
                hsum[h] += __shfl_xor_sync(0xffffffffu, hsum[h], 2);
            }
            float s = 0.25f * hsum[cc];
            s = expf(fminf(fmaxf(s, -5.0f), 5.0f));
            pscore[(size_t)(e0 + mb + er) * NH + hbase + cc] = s;
        }
    }
}

// ---------------- gather: one warp per node, fp16 V ----------------------------
__global__ __launch_bounds__(256)
void gather_kernel(const int* __restrict__ base,
                   const int* __restrict__ psrc,
                   const float* __restrict__ pscore,
                   const __half* __restrict__ V,
                   float* __restrict__ out) {
    const int node = (blockIdx.x * blockDim.x + threadIdx.x) >> 5;
    const int lane = threadIdx.x & 31;
    if (node >= N_NODES) return;

    const int b = base[node];
    const int e = base[node + 1];
    const int h = lane >> 2;

    float4 acc = make_float4(0.f, 0.f, 0.f, 0.f);
    float z = 0.f;

    for (int cb = b; cb < e; cb += 32) {
        const int n = min(32, e - cb);
        int mysrc = 0;
        if (cb + lane < e) mysrc = __ldg(psrc + cb + lane);

        int i = 0;
        for (; i + 8 <= n; i += 8) {
#pragma unroll
            for (int u = 0; u < 8; u++) {
                const int src = __shfl_sync(0xffffffffu, mysrc, i + u);
                const float s = __ldg(pscore + (size_t)(cb + i + u) * NH + h);
                const float4 v = h4_to_f4(__ldg((const uint2*)(V + (size_t)src * DIM) + lane));
                acc.x = fmaf(v.x, s, acc.x);
                acc.y = fmaf(v.y, s, acc.y);
                acc.z = fmaf(v.z, s, acc.z);
                acc.w = fmaf(v.w, s, acc.w);
                z += s;
            }
        }
        for (; i < n; i++) {
            const int src = __shfl_sync(0xffffffffu, mysrc, i);
            const float s = __ldg(pscore + (size_t)(cb + i) * NH + h);
            const float4 v = h4_to_f4(__ldg((const uint2*)(V + (size_t)src * DIM) + lane));
            acc.x = fmaf(v.x, s, acc.x);
            acc.y = fmaf(v.y, s, acc.y);
            acc.z = fmaf(v.z, s, acc.z);
            acc.w = fmaf(v.w, s, acc.w);
            z += s;
        }
    }
    const float inv = 1.0f / (z + 1e-6f);
    *(float4*)(out + (size_t)node * DIM + lane * 4) =
        make_float4(acc.x * inv, acc.y * inv, acc.z * inv, acc.w * inv);
}

// ---------------- launch --------------------------------------------------------
extern "C" void kernel_launch(void* const* d_in, const int* in_sizes, int n_in,
                              void* d_out, int out_size) {
    const float* h   = (const float*)d_in[0];
    const float* ea  = (const float*)d_in[1];
    const float* WQ  = (const float*)d_in[2];
    const float* WK  = (const float*)d_in[3];
    const float* WV  = (const float*)d_in[4];
    const float* WE  = (const float*)d_in[5];
    const void*  eix = d_in[6];
    float* out = (float*)d_out;

    void *qp, *kp, *vp, *cntp, *basep, *psrcp, *pdstp, *pinvp, *pscorep;
    cudaGetSymbolAddress(&qp,      g_Q);
    cudaGetSymbolAddress(&kp,      g_K);
    cudaGetSymbolAddress(&vp,      g_V);
    cudaGetSymbolAddress(&cntp,    g_cnt);
    cudaGetSymbolAddress(&basep,   g_base);
    cudaGetSymbolAddress(&psrcp,   g_psrc);
    cudaGetSymbolAddress(&pdstp,   g_pdst);
    cudaGetSymbolAddress(&pinvp,   g_pinv);
    cudaGetSymbolAddress(&pscorep, g_pscore);

    detect_idx_kernel<<<1, 1>>>(eix);

    // CSR build
    cudaMemsetAsync(cntp, 0, N_NODES * sizeof(int));
    hist_kernel<<<(N_EDGES + 255) / 256, 256>>>(eix, (int*)cntp);
    scan_kernel<<<1, 1024>>>((const int*)cntp, (int*)basep);
    cudaMemsetAsync(cntp, 0, N_NODES * sizeof(int));
    convert_kernel<<<(N_EDGES + 255) / 256, 256>>>(
        eix, (const int*)basep, (int*)cntp,
        (int*)psrcp, (int*)pdstp, (int*)pinvp);

    // node projections (fp32 math, fp16 storage)
    dim3 gN((N_NODES + BM - 1) / BM, 3);
    sgemm3_kernel<<<gN, 256>>>(h, WQ, WK, WV, (__half*)qp, (__half*)kp,
                               (__half*)vp, N_NODES);

    // fused persistent fp16 edge GEMM + accumulator-resident score (2 CTAs/SM)
    const int smem_bytes = (64 * PADB + 2 * 64 * PADA) * 4;   // 69632
    cudaFuncSetAttribute(fused_edge_kernel,
                         cudaFuncAttributeMaxDynamicSharedMemorySize, smem_bytes);
    fused_edge_kernel<<<NPER, 256, smem_bytes>>>(
        ea, WE, (const __half*)qp, (const __half*)kp,
        (const int*)psrcp, (const int*)pdstp, (const int*)pinvp,
        (float*)pscorep);

    // gather + normalize (one warp per node)
    gather_kernel<<<(N_NODES * 32 + 255) / 256, 256>>>(
        (const int*)basep, (const int*)psrcp, (const float*)pscorep,
        (const __half*)vp, out);
}

// round 15
// speedup vs baseline: 1.2056x; 1.0880x over previous
#include <cuda_runtime.h>
#include <cuda_fp16.h>
#include <cstdint>

#define N_NODES 50000
#define N_EDGES 1600000
#define DIM 128
#define NH 8
#define TILE_E 64
#define NTILES (N_EDGES / TILE_E)   // 25000
#define NPER 304                    // persistent CTAs (2 per SM x 152 SMs)
#define PADA 68                     // A tile row stride (half2 units)
#define PADB 136                    // B tile row stride (half2 units)

// ---------------- scratch (static device globals: no alloc allowed) ----------
__device__ __half g_Q[(size_t)N_NODES * DIM];
__device__ __half g_K[(size_t)N_NODES * DIM];
__device__ __half g_V[(size_t)N_NODES * DIM];
__device__ int    g_cnt[N_NODES];
__device__ int    g_base[N_NODES + 1];
__device__ int    g_psrc[N_EDGES];     // slot -> src node
__device__ int    g_pdst[N_EDGES];     // slot -> dst node
__device__ int    g_pinv[N_EDGES];     // slot -> original edge id
__device__ float  g_pscore[(size_t)N_EDGES * NH];   // 51 MB
__device__ int    g_idx64;

// ---------------- edge_index dtype detection (int64 vs int32) ----------------
__global__ void detect_idx_kernel(const void* idx) {
    const long long* p = (const long long*)idx;
    int is64 = 1;
    for (int i = 0; i < 64; i++) {
        long long v = p[i];
        if (v < 0 || v >= N_NODES) { is64 = 0; break; }
    }
    g_idx64 = is64;
}

// ---------------- histogram of dst (simple, measured-best) --------------------
__global__ __launch_bounds__(256)
void hist_kernel(const void* __restrict__ eidx, int* __restrict__ cnt) {
    const int i = blockIdx.x * blockDim.x + threadIdx.x;
    if (i >= N_EDGES) return;
    int dst;
    if (g_idx64) dst = (int)((const long long*)eidx)[(size_t)N_EDGES + i];
    else         dst = ((const int*)eidx)[N_EDGES + i];
    atomicAdd(&cnt[dst], 1);
}

// ---------------- single-block exclusive scan (1024 threads) ------------------
__global__ __launch_bounds__(1024)
void scan_kernel(const int* __restrict__ cnt, int* __restrict__ base) {
    __shared__ int wsum[32];
    const int tid = threadIdx.x;
    const int lane = tid & 31, wid = tid >> 5;
    const int CH = (N_NODES + 1023) / 1024;   // 49
    const int start = tid * CH;

    int s = 0;
    for (int i = 0; i < CH; i++) {
        const int idx = start + i;
        if (idx < N_NODES) s += cnt[idx];
    }
    int v = s;
#pragma unroll
    for (int d = 1; d < 32; d <<= 1) {
        int n = __shfl_up_sync(0xffffffffu, v, d);
        if (lane >= d) v += n;
    }
    if (lane == 31) wsum[wid] = v;
    __syncthreads();
    if (wid == 0) {
        int wv = wsum[lane];
#pragma unroll
        for (int d = 1; d < 32; d <<= 1) {
            int n = __shfl_up_sync(0xffffffffu, wv, d);
            if (lane >= d) wv += n;
        }
        wsum[lane] = wv;
    }
    __syncthreads();
    int run = v - s + (wid > 0 ? wsum[wid - 1] : 0);
    for (int i = 0; i < CH; i++) {
        const int idx = start + i;
        if (idx < N_NODES) { base[idx] = run; run += cnt[idx]; }
    }
    if (tid == 1023) base[N_NODES] = run;
}

// ---------------- convert: CSR slot assignment (simple, measured-best) --------
__global__ __launch_bounds__(256)
void convert_kernel(const void* __restrict__ eidx,
                    const int* __restrict__ base, int* __restrict__ cnt,
                    int* __restrict__ psrc, int* __restrict__ pdst,
                    int* __restrict__ pinv) {
    const int i = blockIdx.x * blockDim.x + threadIdx.x;
    if (i >= N_EDGES) return;
    int s, d;
    if (g_idx64) {
        const long long* p = (const long long*)eidx;
        s = (int)p[i];
        d = (int)p[(size_t)N_EDGES + i];
    } else {
        const int* p = (const int*)eidx;
        s = p[i];
        d = p[N_EDGES + i];
    }
    const int pp = base[d] + atomicAdd(&cnt[d], 1);
    psrc[pp] = s;
    pdst[pp] = d;
    pinv[pp] = i;
}

// ---------------- fp16 helpers -------------------------------------------------
__device__ __forceinline__ uint32_t f2h2(float lo, float hi) {
    __half2 h = __floats2half2_rn(lo, hi);
    return *(uint32_t*)&h;
}

__device__ __forceinline__ float4 h4_to_f4(uint2 raw) {
    const float2 lo = __half22float2(*(__half2*)&raw.x);
    const float2 hi = __half22float2(*(__half2*)&raw.y);
    return make_float4(lo.x, lo.y, hi.x, hi.y);
}

__device__ __forceinline__ void mma_f16(float* d, const uint32_t* a, const uint32_t* b) {
    asm volatile(
        "mma.sync.aligned.m16n8k16.row.col.f32.f16.f16.f32 "
        "{%0,%1,%2,%3}, {%4,%5,%6,%7}, {%8,%9}, {%0,%1,%2,%3};"
        : "+f"(d[0]), "+f"(d[1]), "+f"(d[2]), "+f"(d[3])
        : "r"(a[0]), "r"(a[1]), "r"(a[2]), "r"(a[3]),
          "r"(b[0]), "r"(b[1]));
}

// ---------------- node projections: split-A fp16 tensor-core GEMM -------------
// A = hi + lo (lo = exact fp32 residual rounded to fp16); D = hi@W + lo@W in one
// fp32 accumulator -> error dominated by W's 10-bit rounding (tf32-quality).
// Warp layout identical to fused kernel: warp w -> rows (w&3)*16.., cols (w>>2)*64..
__global__ __launch_bounds__(256, 2)
void sgemm3_mma_kernel(const float* __restrict__ A,
                       const float* __restrict__ WQ, const float* __restrict__ WK,
                       const float* __restrict__ WV,
                       __half* __restrict__ Q, __half* __restrict__ K,
                       __half* __restrict__ V, int M) {
    const float* W = (blockIdx.y == 0) ? WQ : (blockIdx.y == 1) ? WK : WV;
    __half*      C = (blockIdx.y == 0) ? Q  : (blockIdx.y == 1) ? K  : V;

    extern __shared__ uint32_t smem[];
    uint32_t* B2   = smem;                       // [64][PADB] half2 (W, k-paired)
    uint32_t* A2hi = B2 + 64 * PADB;             // [64][PADA] half2
    uint32_t* A2lo = A2hi + 64 * PADA;           // [64][PADA] half2

    const int tid  = threadIdx.x;
    const int lane = tid & 31;
    const int w    = tid >> 5;
    const int m0   = blockIdx.x * 64;

    // ---- load W (128x128) into SMEM as half2 along k ----
    for (int idx = tid; idx < 64 * DIM; idx += 256) {
        const int kk = idx >> 7;
        const int n  = idx & 127;
        B2[kk * PADB + n] = f2h2(__ldg(W + (size_t)(2 * kk) * DIM + n),
                                 __ldg(W + (size_t)(2 * kk + 1) * DIM + n));
    }

    // ---- load A tile (rows m0..m0+63), split hi/lo ----
#pragma unroll
    for (int i = 0; i < 8; i++) {
        const int r  = w + 8 * i;
        const int gr = m0 + r;
        float4 av = make_float4(0.f, 0.f, 0.f, 0.f);
        if (gr < M) av = __ldg((const float4*)(A + (size_t)gr * DIM) + lane);
        const __half hx = __float2half_rn(av.x), hy = __float2half_rn(av.y);
        const __half hz = __float2half_rn(av.z), hw = __float2half_rn(av.w);
        __half2 p0 = __halves2half2(hx, hy), p1 = __halves2half2(hz, hw);
        A2hi[r * PADA + lane * 2]     = *(uint32_t*)&p0;
        A2hi[r * PADA + lane * 2 + 1] = *(uint32_t*)&p1;
        A2lo[r * PADA + lane * 2]     = f2h2(av.x - __half2float(hx),
                                             av.y - __half2float(hy));
        A2lo[r * PADA + lane * 2 + 1] = f2h2(av.z - __half2float(hz),
                                             av.w - __half2float(hw));
    }
    __syncthreads();

    const int g  = lane >> 2;
    const int cc = lane & 3;
    const int mb = (w & 3) * 16;
    const int nb = (w >> 2) * 64;

    float acc[8][4];
#pragma unroll
    for (int nt = 0; nt < 8; nt++)
#pragma unroll
        for (int q = 0; q < 4; q++) acc[nt][q] = 0.0f;

#pragma unroll
    for (int ks = 0; ks < 8; ks++) {
        const int kk = 8 * ks + cc;
        uint32_t ah[4], al[4];
        ah[0] = A2hi[(mb + g) * PADA + kk];
        ah[1] = A2hi[(mb + g + 8) * PADA + kk];
        ah[2] = A2hi[(mb + g) * PADA + kk + 4];
        ah[3] = A2hi[(mb + g + 8) * PADA + kk + 4];
        al[0] = A2lo[(mb + g) * PADA + kk];
        al[1] = A2lo[(mb + g + 8) * PADA + kk];
        al[2] = A2lo[(mb + g) * PADA + kk + 4];
        al[3] = A2lo[(mb + g + 8) * PADA + kk + 4];
        uint32_t b[8][2];
#pragma unroll
        for (int nt = 0; nt < 8; nt++) {
            const int n = nb + 8 * nt + g;
            b[nt][0] = B2[kk * PADB + n];
            b[nt][1] = B2[(kk + 4) * PADB + n];
        }
#pragma unroll
        for (int nt = 0; nt < 8; nt++) {
            mma_f16(acc[nt], ah, b[nt]);
            mma_f16(acc[nt], al, b[nt]);
        }
    }

    // ---- store C as fp16 ----
#pragma unroll
    for (int half = 0; half < 2; half++) {
        const int row = m0 + mb + g + 8 * half;
        if (row < M) {
#pragma unroll
            for (int nt = 0; nt < 8; nt++) {
                __half2 hv = __floats2half2_rn(acc[nt][2 * half], acc[nt][2 * half + 1]);
                *(__half2*)(C + (size_t)row * DIM + nb + 8 * nt + 2 * cc) = hv;
            }
        }
    }
}

// ---------------- fused edge kernel: accumulator-resident epilogue ------------
__global__ __launch_bounds__(256, 2)
void fused_edge_kernel(const float* __restrict__ ea,
                       const float* __restrict__ WE,
                       const __half* __restrict__ Q,
                       const __half* __restrict__ K,
                       const int* __restrict__ psrc,
                       const int* __restrict__ pdst,
                       const int* __restrict__ pinv,
                       float* __restrict__ pscore) {
    extern __shared__ uint32_t smem[];
    uint32_t* B2 = smem;                         // [64][PADB] half2 (WE, k-paired)
    uint32_t* A2b[2];
    A2b[0] = B2 + 64 * PADB;                     // [64][PADA] half2, buffer 0
    A2b[1] = A2b[0] + 64 * PADA;                 // buffer 1

    const int tid  = threadIdx.x;
    const int lane = tid & 31;
    const int w    = tid >> 5;                   // 0..7

    // ---- load WE (128x128) into SMEM as half2 along k — ONCE per CTA ----
    for (int idx = tid; idx < 64 * DIM; idx += 256) {
        const int kk = idx >> 7;
        const int n  = idx & 127;
        const float w0 = __ldg(WE + (size_t)(2 * kk) * DIM + n);
        const float w1 = __ldg(WE + (size_t)(2 * kk + 1) * DIM + n);
        B2[kk * PADB + n] = f2h2(w0, w1);
    }

    const int cnt = 82 + (blockIdx.x < (NTILES - NPER * 82) ? 1 : 0);

    float4 areg[8];
    auto prefetchA = [&](int tile) {
        const int e0 = tile * TILE_E;
        int myp = 0;
        if (lane < 8) myp = __ldg(pinv + e0 + w + 8 * lane);
#pragma unroll
        for (int i = 0; i < 8; i++) {
            const int eid = __shfl_sync(0xffffffffu, myp, i);
            areg[i] = __ldg((const float4*)(ea + (size_t)eid * DIM) + lane);
        }
    };

    prefetchA(blockIdx.x);   // prologue

    const int g  = lane >> 2;
    const int cc = lane & 3;
    const int mb = (w & 3) * 16;    // 16-edge block
    const int nb = (w >> 2) * 64;   // 64-col block (4 heads)
    const int hbase = (w >> 2) * 4; // global head base

    for (int j = 0; j < cnt; j++) {
        const int tile = blockIdx.x + j * NPER;
        const int e0   = tile * TILE_E;
        uint32_t* A2 = A2b[j & 1];

#pragma unroll
        for (int i = 0; i < 8; i++) {
            const int r = w + 8 * i;
            A2[r * PADA + lane * 2]     = f2h2(areg[i].x, areg[i].y);
            A2[r * PADA + lane * 2 + 1] = f2h2(areg[i].z, areg[i].w);
        }
        if (j + 1 < cnt) prefetchA(blockIdx.x + (j + 1) * NPER);

        int idxreg;
        if (lane < 16) idxreg = __ldg(psrc + e0 + mb + lane);
        else           idxreg = __ldg(pdst + e0 + mb + (lane - 16));

        __syncthreads();   // A(j) visible to all warps

        float acc[8][4];
#pragma unroll
        for (int nt = 0; nt < 8; nt++)
#pragma unroll
            for (int q = 0; q < 4; q++) acc[nt][q] = 0.0f;

#pragma unroll
        for (int ks = 0; ks < 8; ks++) {
            const int kk = 8 * ks + cc;
            uint32_t a[4];
            a[0] = A2[(mb + g) * PADA + kk];
            a[1] = A2[(mb + g + 8) * PADA + kk];
            a[2] = A2[(mb + g) * PADA + kk + 4];
            a[3] = A2[(mb + g + 8) * PADA + kk + 4];
            uint32_t b[8][2];
#pragma unroll
            for (int nt = 0; nt < 8; nt++) {
                const int n = nb + 8 * nt + g;
                b[nt][0] = B2[kk * PADB + n];
                b[nt][1] = B2[(kk + 4) * PADB + n];
            }
#pragma unroll
            for (int nt = 0; nt < 8; nt++)
                mma_f16(acc[nt], a, b[nt]);
        }

#pragma unroll
        for (int half = 0; half < 2; half++) {
            const int er  = g + 8 * half;
            const int src = __shfl_sync(0xffffffffu, idxreg, er);
            const int dst = __shfl_sync(0xffffffffu, idxreg, 16 + er);
            const __half* Kp = K + (size_t)src * DIM;
            const __half* Qp = Q + (size_t)dst * DIM;

            float hsum[4] = {0.f, 0.f, 0.f, 0.f};
#pragma unroll
            for (int chunk = 0; chunk < 2; chunk++) {
                float2 k2[4], q2[4];
#pragma unroll
                for (int t = 0; t < 4; t++) {
                    const int col = nb + 8 * (4 * chunk + t) + 2 * cc;
                    k2[t] = __half22float2(__ldg((const __half2*)(Kp + col)));
                    q2[t] = __half22float2(__ldg((const __half2*)(Qp + col)));
                }
#pragma unroll
                for (int t = 0; t < 4; t++) {
                    const int nt = 4 * chunk + t;
                    hsum[nt >> 1] += acc[nt][2 * half]     * k2[t].x * q2[t].x
                                   + acc[nt][2 * half + 1] * k2[t].y * q2[t].y;
                }
            }
#pragma unroll
            for (int h = 0; h < 4; h++) {
                hsum[h] += __shfl_xor_sync(0xffffffffu, hsum[h], 1);
                hsum[h] += __shfl_xor_sync(0xffffffffu, hsum[h], 2);
            }
            float s = 0.25f * hsum[cc];
            s = expf(fminf(fmaxf(s, -5.0f), 5.0f));
            pscore[(size_t)(e0 + mb + er) * NH + hbase + cc] = s;
        }
    }
}

// ---------------- gather: one warp per node, fp16 V ----------------------------
__global__ __launch_bounds__(256)
void gather_kernel(const int* __restrict__ base,
                   const int* __restrict__ psrc,
                   const float* __restrict__ pscore,
                   const __half* __restrict__ V,
                   float* __restrict__ out) {
    const int node = (blockIdx.x * blockDim.x + threadIdx.x) >> 5;
    const int lane = threadIdx.x & 31;
    if (node >= N_NODES) return;

    const int b = base[node];
    const int e = base[node + 1];
    const int h = lane >> 2;

    float4 acc = make_float4(0.f, 0.f, 0.f, 0.f);
    float z = 0.f;

    for (int cb = b; cb < e; cb += 32) {
        const int n = min(32, e - cb);
        int mysrc = 0;
        if (cb + lane < e) mysrc = __ldg(psrc + cb + lane);

        int i = 0;
        for (; i + 8 <= n; i += 8) {
#pragma unroll
            for (int u = 0; u < 8; u++) {
                const int src = __shfl_sync(0xffffffffu, mysrc, i + u);
                const float s = __ldg(pscore + (size_t)(cb + i + u) * NH + h);
                const float4 v = h4_to_f4(__ldg((const uint2*)(V + (size_t)src * DIM) + lane));
                acc.x = fmaf(v.x, s, acc.x);
                acc.y = fmaf(v.y, s, acc.y);
                acc.z = fmaf(v.z, s, acc.z);
                acc.w = fmaf(v.w, s, acc.w);
                z += s;
            }
        }
        for (; i < n; i++) {
            const int src = __shfl_sync(0xffffffffu, mysrc, i);
            const float s = __ldg(pscore + (size_t)(cb + i) * NH + h);
            const float4 v = h4_to_f4(__ldg((const uint2*)(V + (size_t)src * DIM) + lane));
            acc.x = fmaf(v.x, s, acc.x);
            acc.y = fmaf(v.y, s, acc.y);
            acc.z = fmaf(v.z, s, acc.z);
            acc.w = fmaf(v.w, s, acc.w);
            z += s;
        }
    }
    const float inv = 1.0f / (z + 1e-6f);
    *(float4*)(out + (size_t)node * DIM + lane * 4) =
        make_float4(acc.x * inv, acc.y * inv, acc.z * inv, acc.w * inv);
}

// ---------------- launch --------------------------------------------------------
extern "C" void kernel_launch(void* const* d_in, const int* in_sizes, int n_in,
                              void* d_out, int out_size) {
    const float* h   = (const float*)d_in[0];
    const float* ea  = (const float*)d_in[1];
    const float* WQ  = (const float*)d_in[2];
    const float* WK  = (const float*)d_in[3];
    const float* WV  = (const float*)d_in[4];
    const float* WE  = (const float*)d_in[5];
    const void*  eix = d_in[6];
    float* out = (float*)d_out;

    void *qp, *kp, *vp, *cntp, *basep, *psrcp, *pdstp, *pinvp, *pscorep;
    cudaGetSymbolAddress(&qp,      g_Q);
    cudaGetSymbolAddress(&kp,      g_K);
    cudaGetSymbolAddress(&vp,      g_V);
    cudaGetSymbolAddress(&cntp,    g_cnt);
    cudaGetSymbolAddress(&basep,   g_base);
    cudaGetSymbolAddress(&psrcp,   g_psrc);
    cudaGetSymbolAddress(&pdstp,   g_pdst);
    cudaGetSymbolAddress(&pinvp,   g_pinv);
    cudaGetSymbolAddress(&pscorep, g_pscore);

    detect_idx_kernel<<<1, 1>>>(eix);

    // CSR build
    cudaMemsetAsync(cntp, 0, N_NODES * sizeof(int));
    hist_kernel<<<(N_EDGES + 255) / 256, 256>>>(eix, (int*)cntp);
    scan_kernel<<<1, 1024>>>((const int*)cntp, (int*)basep);
    cudaMemsetAsync(cntp, 0, N_NODES * sizeof(int));
    convert_kernel<<<(N_EDGES + 255) / 256, 256>>>(
        eix, (const int*)basep, (int*)cntp,
        (int*)psrcp, (int*)pdstp, (int*)pinvp);

    const int smem_bytes = (64 * PADB + 2 * 64 * PADA) * 4;   // 69632

    // node projections: split-A fp16 tensor-core GEMM (tf32-quality)
    cudaFuncSetAttribute(sgemm3_mma_kernel,
                         cudaFuncAttributeMaxDynamicSharedMemorySize, smem_bytes);
    dim3 gN((N_NODES + 63) / 64, 3);
    sgemm3_mma_kernel<<<gN, 256, smem_bytes>>>(h, WQ, WK, WV, (__half*)qp,
                                               (__half*)kp, (__half*)vp, N_NODES);

    // fused persistent fp16 edge GEMM + accumulator-resident score (2 CTAs/SM)
    cudaFuncSetAttribute(fused_edge_kernel,
                         cudaFuncAttributeMaxDynamicSharedMemorySize, smem_bytes);
    fused_edge_kernel<<<NPER, 256, smem_bytes>>>(
        ea, WE, (const __half*)qp, (const __half*)kp,
        (const int*)psrcp, (const int*)pdstp, (const int*)pinvp,
        (float*)pscorep);

    // gather + normalize (one warp per node)
    gather_kernel<<<(N_NODES * 32 + 255) / 256, 256>>>(
        (const int*)basep, (const int*)psrcp, (const float*)pscorep,
        (const __half*)vp, out);
}

// round 16
// speedup vs baseline: 1.2545x; 1.0405x over previous
#include <cuda_runtime.h>
#include <cuda_fp16.h>
#include <cstdint>

#define N_NODES 50000
#define N_EDGES 1600000
#define DIM 128
#define NH 8
#define TILE_E 64
#define NTILES (N_EDGES / TILE_E)   // 25000
#define NPER 304                    // persistent CTAs (2 per SM x 152 SMs)
#define PADA 68                     // A tile row stride (half2 units)
#define PADB 136                    // B tile row stride (half2 units)
#define GEMM_BLKS 782               // ceil(50000/64)

// ---------------- scratch (static device globals: no alloc allowed) ----------
__device__ __half g_Q[(size_t)N_NODES * DIM];
__device__ __half g_K[(size_t)N_NODES * DIM];
__device__ __half g_V[(size_t)N_NODES * DIM];
__device__ int    g_cnt[N_NODES];
__device__ int    g_base[N_NODES + 1];
__device__ int4   g_edge4[N_EDGES];    // slot -> {src, dst, orig edge id, 0}
__device__ float  g_pscore[(size_t)N_EDGES * NH];   // 51 MB
__device__ int    g_idx64;

// ---------------- edge_index dtype detection (int64 vs int32) ----------------
__global__ void detect_idx_kernel(const void* idx) {
    const long long* p = (const long long*)idx;
    int is64 = 1;
    for (int i = 0; i < 64; i++) {
        long long v = p[i];
        if (v < 0 || v >= N_NODES) { is64 = 0; break; }
    }
    g_idx64 = is64;
}

// ---------------- single-block exclusive scan (1024 threads) ------------------
__global__ __launch_bounds__(1024)
void scan_kernel(const int* __restrict__ cnt, int* __restrict__ base) {
    __shared__ int wsum[32];
    const int tid = threadIdx.x;
    const int lane = tid & 31, wid = tid >> 5;
    const int CH = (N_NODES + 1023) / 1024;   // 49
    const int start = tid * CH;

    int s = 0;
    for (int i = 0; i < CH; i++) {
        const int idx = start + i;
        if (idx < N_NODES) s += cnt[idx];
    }
    int v = s;
#pragma unroll
    for (int d = 1; d < 32; d <<= 1) {
        int n = __shfl_up_sync(0xffffffffu, v, d);
        if (lane >= d) v += n;
    }
    if (lane == 31) wsum[wid] = v;
    __syncthreads();
    if (wid == 0) {
        int wv = wsum[lane];
#pragma unroll
        for (int d = 1; d < 32; d <<= 1) {
            int n = __shfl_up_sync(0xffffffffu, wv, d);
            if (lane >= d) wv += n;
        }
        wsum[lane] = wv;
    }
    __syncthreads();
    int run = v - s + (wid > 0 ? wsum[wid - 1] : 0);
    for (int i = 0; i < CH; i++) {
        const int idx = start + i;
        if (idx < N_NODES) { base[idx] = run; run += cnt[idx]; }
    }
    if (tid == 1023) base[N_NODES] = run;
}

// ---------------- convert: CSR slot assignment, single int4 store -------------
__global__ __launch_bounds__(256)
void convert_kernel(const void* __restrict__ eidx,
                    const int* __restrict__ base, int* __restrict__ cnt,
                    int4* __restrict__ edge4) {
    const int i = blockIdx.x * blockDim.x + threadIdx.x;
    if (i >= N_EDGES) return;
    int s, d;
    if (g_idx64) {
        const long long* p = (const long long*)eidx;
        s = (int)p[i];
        d = (int)p[(size_t)N_EDGES + i];
    } else {
        const int* p = (const int*)eidx;
        s = p[i];
        d = p[N_EDGES + i];
    }
    const int pp = base[d] + atomicAdd(&cnt[d], 1);
    edge4[pp] = make_int4(s, d, i, 0);
}

// ---------------- fp16 helpers -------------------------------------------------
__device__ __forceinline__ uint32_t f2h2(float lo, float hi) {
    __half2 h = __floats2half2_rn(lo, hi);
    return *(uint32_t*)&h;
}

__device__ __forceinline__ float4 h4_to_f4(uint2 raw) {
    const float2 lo = __half22float2(*(__half2*)&raw.x);
    const float2 hi = __half22float2(*(__half2*)&raw.y);
    return make_float4(lo.x, lo.y, hi.x, hi.y);
}

__device__ __forceinline__ void mma_f16(float* d, const uint32_t* a, const uint32_t* b) {
    asm volatile(
        "mma.sync.aligned.m16n8k16.row.col.f32.f16.f16.f32 "
        "{%0,%1,%2,%3}, {%4,%5,%6,%7}, {%8,%9}, {%0,%1,%2,%3};"
        : "+f"(d[0]), "+f"(d[1]), "+f"(d[2]), "+f"(d[3])
        : "r"(a[0]), "r"(a[1]), "r"(a[2]), "r"(a[3]),
          "r"(b[0]), "r"(b[1]));
}

// ---------------- projections (split-A fp16 mma) + hist, ONE launch -----------
// Blocks [0, 3*GEMM_BLKS): node projection GEMMs (identical math to R15).
// Blocks [3*GEMM_BLKS, +304): grid-stride dst histogram (hidden under GEMM).
__global__ __launch_bounds__(256, 2)
void sgemm3h_kernel(const float* __restrict__ A,
                    const float* __restrict__ WQ, const float* __restrict__ WK,
                    const float* __restrict__ WV,
                    __half* __restrict__ Q, __half* __restrict__ K,
                    __half* __restrict__ V, int M,
                    const void* __restrict__ eidx, int* __restrict__ cnt) {
    if (blockIdx.x >= 3 * GEMM_BLKS) {
        // ---- histogram path (grid-stride over edges) ----
        const bool idx64 = (g_idx64 != 0);
        const int stride = NPER * 256;
        for (int i = (blockIdx.x - 3 * GEMM_BLKS) * 256 + threadIdx.x;
             i < N_EDGES; i += stride) {
            int dst;
            if (idx64) dst = (int)__ldg((const long long*)eidx + (size_t)N_EDGES + i);
            else       dst = __ldg((const int*)eidx + N_EDGES + i);
            atomicAdd(&cnt[dst], 1);
        }
        return;
    }

    const int mat = blockIdx.x / GEMM_BLKS;
    const float* W = (mat == 0) ? WQ : (mat == 1) ? WK : WV;
    __half*      C = (mat == 0) ? Q  : (mat == 1) ? K  : V;
    const int m0 = (blockIdx.x % GEMM_BLKS) * 64;

    extern __shared__ uint32_t smem[];
    uint32_t* B2   = smem;                       // [64][PADB] half2 (W, k-paired)
    uint32_t* A2hi = B2 + 64 * PADB;             // [64][PADA] half2
    uint32_t* A2lo = A2hi + 64 * PADA;           // [64][PADA] half2

    const int tid  = threadIdx.x;
    const int lane = tid & 31;
    const int w    = tid >> 5;

    for (int idx = tid; idx < 64 * DIM; idx += 256) {
        const int kk = idx >> 7;
        const int n  = idx & 127;
        B2[kk * PADB + n] = f2h2(__ldg(W + (size_t)(2 * kk) * DIM + n),
                                 __ldg(W + (size_t)(2 * kk + 1) * DIM + n));
    }

#pragma unroll
    for (int i = 0; i < 8; i++) {
        const int r  = w + 8 * i;
        const int gr = m0 + r;
        float4 av = make_float4(0.f, 0.f, 0.f, 0.f);
        if (gr < M) av = __ldg((const float4*)(A + (size_t)gr * DIM) + lane);
        const __half hx = __float2half_rn(av.x), hy = __float2half_rn(av.y);
        const __half hz = __float2half_rn(av.z), hw = __float2half_rn(av.w);
        __half2 p0 = __halves2half2(hx, hy), p1 = __halves2half2(hz, hw);
        A2hi[r * PADA + lane * 2]     = *(uint32_t*)&p0;
        A2hi[r * PADA + lane * 2 + 1] = *(uint32_t*)&p1;
        A2lo[r * PADA + lane * 2]     = f2h2(av.x - __half2float(hx),
                                             av.y - __half2float(hy));
        A2lo[r * PADA + lane * 2 + 1] = f2h2(av.z - __half2float(hz),
                                             av.w - __half2float(hw));
    }
    __syncthreads();

    const int g  = lane >> 2;
    const int cc = lane & 3;
    const int mb = (w & 3) * 16;
    const int nb = (w >> 2) * 64;

    float acc[8][4];
#pragma unroll
    for (int nt = 0; nt < 8; nt++)
#pragma unroll
        for (int q = 0; q < 4; q++) acc[nt][q] = 0.0f;

#pragma unroll
    for (int ks = 0; ks < 8; ks++) {
        const int kk = 8 * ks + cc;
        uint32_t ah[4], al[4];
        ah[0] = A2hi[(mb + g) * PADA + kk];
        ah[1] = A2hi[(mb + g + 8) * PADA + kk];
        ah[2] = A2hi[(mb + g) * PADA + kk + 4];
        ah[3] = A2hi[(mb + g + 8) * PADA + kk + 4];
        al[0] = A2lo[(mb + g) * PADA + kk];
        al[1] = A2lo[(mb + g + 8) * PADA + kk];
        al[2] = A2lo[(mb + g) * PADA + kk + 4];
        al[3] = A2lo[(mb + g + 8) * PADA + kk + 4];
        uint32_t b[8][2];
#pragma unroll
        for (int nt = 0; nt < 8; nt++) {
            const int n = nb + 8 * nt + g;
            b[nt][0] = B2[kk * PADB + n];
            b[nt][1] = B2[(kk + 4) * PADB + n];
        }
#pragma unroll
        for (int nt = 0; nt < 8; nt++) {
            mma_f16(acc[nt], ah, b[nt]);
            mma_f16(acc[nt], al, b[nt]);
        }
    }

#pragma unroll
    for (int half = 0; half < 2; half++) {
        const int row = m0 + mb + g + 8 * half;
        if (row < M) {
#pragma unroll
            for (int nt = 0; nt < 8; nt++) {
                __half2 hv = __floats2half2_rn(acc[nt][2 * half], acc[nt][2 * half + 1]);
                *(__half2*)(C + (size_t)row * DIM + nb + 8 * nt + 2 * cc) = hv;
            }
        }
    }
}

// ---------------- fused edge kernel: accumulator-resident epilogue ------------
__global__ __launch_bounds__(256, 2)
void fused_edge_kernel(const float* __restrict__ ea,
                       const float* __restrict__ WE,
                       const __half* __restrict__ Q,
                       const __half* __restrict__ K,
                       const int4* __restrict__ edge4,
                       float* __restrict__ pscore) {
    extern __shared__ uint32_t smem[];
    uint32_t* B2 = smem;                         // [64][PADB] half2 (WE, k-paired)
    uint32_t* A2b[2];
    A2b[0] = B2 + 64 * PADB;                     // [64][PADA] half2, buffer 0
    A2b[1] = A2b[0] + 64 * PADA;                 // buffer 1

    const int tid  = threadIdx.x;
    const int lane = tid & 31;
    const int w    = tid >> 5;                   // 0..7

    for (int idx = tid; idx < 64 * DIM; idx += 256) {
        const int kk = idx >> 7;
        const int n  = idx & 127;
        const float w0 = __ldg(WE + (size_t)(2 * kk) * DIM + n);
        const float w1 = __ldg(WE + (size_t)(2 * kk + 1) * DIM + n);
        B2[kk * PADB + n] = f2h2(w0, w1);
    }

    const int cnt = 82 + (blockIdx.x < (NTILES - NPER * 82) ? 1 : 0);

    float4 areg[8];
    auto prefetchA = [&](int tile) {
        const int e0 = tile * TILE_E;
        int myp = 0;
        if (lane < 8)
            myp = __ldg((const int*)(edge4 + e0 + w + 8 * lane) + 2);  // .z = pinv
#pragma unroll
        for (int i = 0; i < 8; i++) {
            const int eid = __shfl_sync(0xffffffffu, myp, i);
            areg[i] = __ldg((const float4*)(ea + (size_t)eid * DIM) + lane);
        }
    };

    prefetchA(blockIdx.x);   // prologue

    const int g  = lane >> 2;
    const int cc = lane & 3;
    const int mb = (w & 3) * 16;    // 16-edge block
    const int nb = (w >> 2) * 64;   // 64-col block (4 heads)
    const int hbase = (w >> 2) * 4; // global head base

    for (int j = 0; j < cnt; j++) {
        const int tile = blockIdx.x + j * NPER;
        const int e0   = tile * TILE_E;
        uint32_t* A2 = A2b[j & 1];

#pragma unroll
        for (int i = 0; i < 8; i++) {
            const int r = w + 8 * i;
            A2[r * PADA + lane * 2]     = f2h2(areg[i].x, areg[i].y);
            A2[r * PADA + lane * 2 + 1] = f2h2(areg[i].z, areg[i].w);
        }
        if (j + 1 < cnt) prefetchA(blockIdx.x + (j + 1) * NPER);

        // ---- (src,dst) for this warp's 16 edges: one int2 per lane<16 ----
        int srcreg = 0, dstreg = 0;
        if (lane < 16) {
            const int2 sd = __ldg((const int2*)(edge4 + e0 + mb + lane));
            srcreg = sd.x;
            dstreg = sd.y;
        }

        __syncthreads();   // A(j) visible to all warps

        float acc[8][4];
#pragma unroll
        for (int nt = 0; nt < 8; nt++)
#pragma unroll
            for (int q = 0; q < 4; q++) acc[nt][q] = 0.0f;

#pragma unroll
        for (int ks = 0; ks < 8; ks++) {
            const int kk = 8 * ks + cc;
            uint32_t a[4];
            a[0] = A2[(mb + g) * PADA + kk];
            a[1] = A2[(mb + g + 8) * PADA + kk];
            a[2] = A2[(mb + g) * PADA + kk + 4];
            a[3] = A2[(mb + g + 8) * PADA + kk + 4];
            uint32_t b[8][2];
#pragma unroll
            for (int nt = 0; nt < 8; nt++) {
                const int n = nb + 8 * nt + g;
                b[nt][0] = B2[kk * PADB + n];
                b[nt][1] = B2[(kk + 4) * PADB + n];
            }
#pragma unroll
            for (int nt = 0; nt < 8; nt++)
                mma_f16(acc[nt], a, b[nt]);
        }

#pragma unroll
        for (int half = 0; half < 2; half++) {
            const int er  = g + 8 * half;
            const int src = __shfl_sync(0xffffffffu, srcreg, er);
            const int dst = __shfl_sync(0xffffffffu, dstreg, er);
            const __half* Kp = K + (size_t)src * DIM;
            const __half* Qp = Q + (size_t)dst * DIM;

            float hsum[4] = {0.f, 0.f, 0.f, 0.f};
#pragma unroll
            for (int chunk = 0; chunk < 2; chunk++) {
                float2 k2[4], q2[4];
#pragma unroll
                for (int t = 0; t < 4; t++) {
                    const int col = nb + 8 * (4 * chunk + t) + 2 * cc;
                    k2[t] = __half22float2(__ldg((const __half2*)(Kp + col)));
                    q2[t] = __half22float2(__ldg((const __half2*)(Qp + col)));
                }
#pragma unroll
                for (int t = 0; t < 4; t++) {
                    const int nt = 4 * chunk + t;
                    hsum[nt >> 1] += acc[nt][2 * half]     * k2[t].x * q2[t].x
                                   + acc[nt][2 * half + 1] * k2[t].y * q2[t].y;
                }
            }
#pragma unroll
            for (int h = 0; h < 4; h++) {
                hsum[h] += __shfl_xor_sync(0xffffffffu, hsum[h], 1);
                hsum[h] += __shfl_xor_sync(0xffffffffu, hsum[h], 2);
            }
            float s = 0.25f * hsum[cc];
            s = expf(fminf(fmaxf(s, -5.0f), 5.0f));
            pscore[(size_t)(e0 + mb + er) * NH + hbase + cc] = s;
        }
    }
}

// ---------------- gather: one warp per node, fp16 V ----------------------------
__global__ __launch_bounds__(256)
void gather_kernel(const int* __restrict__ base,
                   const int4* __restrict__ edge4,
                   const float* __restrict__ pscore,
                   const __half* __restrict__ V,
                   float* __restrict__ out) {
    const int node = (blockIdx.x * blockDim.x + threadIdx.x) >> 5;
    const int lane = threadIdx.x & 31;
    if (node >= N_NODES) return;

    const int b = base[node];
    const int e = base[node + 1];
    const int h = lane >> 2;

    float4 acc = make_float4(0.f, 0.f, 0.f, 0.f);
    float z = 0.f;

    for (int cb = b; cb < e; cb += 32) {
        const int n = min(32, e - cb);
        int mysrc = 0;
        if (cb + lane < e) mysrc = __ldg((const int*)(edge4 + cb + lane));  // .x = src

        int i = 0;
        for (; i + 8 <= n; i += 8) {
#pragma unroll
            for (int u = 0; u < 8; u++) {
                const int src = __shfl_sync(0xffffffffu, mysrc, i + u);
                const float s = __ldg(pscore + (size_t)(cb + i + u) * NH + h);
                const float4 v = h4_to_f4(__ldg((const uint2*)(V + (size_t)src * DIM) + lane));
                acc.x = fmaf(v.x, s, acc.x);
                acc.y = fmaf(v.y, s, acc.y);
                acc.z = fmaf(v.z, s, acc.z);
                acc.w = fmaf(v.w, s, acc.w);
                z += s;
            }
        }
        for (; i < n; i++) {
            const int src = __shfl_sync(0xffffffffu, mysrc, i);
            const float s = __ldg(pscore + (size_t)(cb + i) * NH + h);
            const float4 v = h4_to_f4(__ldg((const uint2*)(V + (size_t)src * DIM) + lane));
            acc.x = fmaf(v.x, s, acc.x);
            acc.y = fmaf(v.y, s, acc.y);
            acc.z = fmaf(v.z, s, acc.z);
            acc.w = fmaf(v.w, s, acc.w);
            z += s;
        }
    }
    const float inv = 1.0f / (z + 1e-6f);
    *(float4*)(out + (size_t)node * DIM + lane * 4) =
        make_float4(acc.x * inv, acc.y * inv, acc.z * inv, acc.w * inv);
}

// ---------------- launch --------------------------------------------------------
extern "C" void kernel_launch(void* const* d_in, const int* in_sizes, int n_in,
                              void* d_out, int out_size) {
    const float* h   = (const float*)d_in[0];
    const float* ea  = (const float*)d_in[1];
    const float* WQ  = (const float*)d_in[2];
    const float* WK  = (const float*)d_in[3];
    const float* WV  = (const float*)d_in[4];
    const float* WE  = (const float*)d_in[5];
    const void*  eix = d_in[6];
    float* out = (float*)d_out;

    void *qp, *kp, *vp, *cntp, *basep, *e4p, *pscorep;
    cudaGetSymbolAddress(&qp,      g_Q);
    cudaGetSymbolAddress(&kp,      g_K);
    cudaGetSymbolAddress(&vp,      g_V);
    cudaGetSymbolAddress(&cntp,    g_cnt);
    cudaGetSymbolAddress(&basep,   g_base);
    cudaGetSymbolAddress(&e4p,     g_edge4);
    cudaGetSymbolAddress(&pscorep, g_pscore);

    detect_idx_kernel<<<1, 1>>>(eix);
    cudaMemsetAsync(cntp, 0, N_NODES * sizeof(int));

    const int smem_bytes = (64 * PADB + 2 * 64 * PADA) * 4;   // 69632

    // node projections + dst histogram in ONE launch
    cudaFuncSetAttribute(sgemm3h_kernel,
                         cudaFuncAttributeMaxDynamicSharedMemorySize, smem_bytes);
    sgemm3h_kernel<<<3 * GEMM_BLKS + NPER, 256, smem_bytes>>>(
        h, WQ, WK, WV, (__half*)qp, (__half*)kp, (__half*)vp, N_NODES,
        eix, (int*)cntp);

    scan_kernel<<<1, 1024>>>((const int*)cntp, (int*)basep);
    cudaMemsetAsync(cntp, 0, N_NODES * sizeof(int));
    convert_kernel<<<(N_EDGES + 255) / 256, 256>>>(
        eix, (const int*)basep, (int*)cntp, (int4*)e4p);

    // fused persistent fp16 edge GEMM + accumulator-resident score (2 CTAs/SM)
    cudaFuncSetAttribute(fused_edge_kernel,
                         cudaFuncAttributeMaxDynamicSharedMemorySize, smem_bytes);
    fused_edge_kernel<<<NPER, 256, smem_bytes>>>(
        ea, WE, (const __half*)qp, (const __half*)kp,
        (const int4*)e4p, (float*)pscorep);

    // gather + normalize (one warp per node)
    gather_kernel<<<(N_NODES * 32 + 255) / 256, 256>>>(
        (const int*)basep, (const int4*)e4p, (const float*)pscorep,
        (const __half*)vp, out);
}